// round 7
// baseline (speedup 1.0000x reference)
#include <cuda_runtime.h>
#include <math.h>

#define BATCH 2
#define SEQ   2048
#define DIM   1024
#define HEADS 16
#define HD    64
#define MROWS (BATCH*SEQ)   // 4096

// Scratch. Referenced ONLY from device code.
__device__ float g_qp[MROWS*DIM];
__device__ float g_kp[MROWS*DIM];
__device__ float g_vp[MROWS*DIM];
__device__ float g_ao[MROWS*DIM];

// ---------------------------------------------------------------------------
// Naive GEMM body: C[m,n] = sum_k A[m,k] * W[k,n] + bias[n].
// ---------------------------------------------------------------------------
__device__ __forceinline__ void gemm_naive_body(const float* __restrict__ A,
                                                const float* __restrict__ W,
                                                const float* __restrict__ bias,
                                                float* __restrict__ C)
{
    int idx = blockIdx.x * 256 + threadIdx.x;
    int m = idx >> 10;
    int n = idx & 1023;
    const float* a = A + (size_t)m * DIM;
    float acc = 0.0f;
#pragma unroll 4
    for (int k = 0; k < DIM; k++)
        acc += a[k] * W[(size_t)k * DIM + n];
    C[idx] = acc + bias[n];
}

__global__ void __launch_bounds__(256) gemm_q_kernel(const float* A, const float* W, const float* b) { gemm_naive_body(A, W, b, g_qp); }
__global__ void __launch_bounds__(256) gemm_k_kernel(const float* A, const float* W, const float* b) { gemm_naive_body(A, W, b, g_kp); }
__global__ void __launch_bounds__(256) gemm_v_kernel(const float* A, const float* W, const float* b) { gemm_naive_body(A, W, b, g_vp); }
__global__ void __launch_bounds__(256) gemm_o_kernel(const float* W, const float* b, float* out)     { gemm_naive_body(g_ao, W, b, out); }

// ---------------------------------------------------------------------------
// RoPE with FLIPPED rotation direction (the single change this round):
// out1 = x1*cos + x2*sin;  out2 = x2*cos - x1*sin   (i.e. angle -> -angle)
// pairs (d, d+32) per head; |angle| = pos * 10000^(-d/32).
// ---------------------------------------------------------------------------
__global__ void __launch_bounds__(256) rope_kernel()
{
    int idx = blockIdx.x * blockDim.x + threadIdx.x;
    if (idx >= MROWS * (DIM / 2)) return;
    int m = idx >> 9;          // row (b*SEQ + l)
    int c = idx & 511;         // 16 heads * 32 pair-dims
    int h = c >> 5;
    int d = c & 31;
    int pos = m & (SEQ - 1);

    float invf = 1.0f / powf(10000.0f, (float)d * (1.0f / 32.0f));
    float ang  = (float)pos * invf;
    float cs, sn;
    sincosf(ang, &cs, &sn);

    int base = m * DIM + h * HD + d;
    float q1 = g_qp[base], q2 = g_qp[base + 32];
    g_qp[base]      = q1 * cs + q2 * sn;   // flipped sign
    g_qp[base + 32] = q2 * cs - q1 * sn;   // flipped sign
    float k1 = g_kp[base], k2 = g_kp[base + 32];
    g_kp[base]      = k1 * cs + k2 * sn;   // flipped sign
    g_kp[base + 32] = k2 * cs - k1 * sn;   // flipped sign
}

// ---------------------------------------------------------------------------
// Naive causal attention (tril mask hardcoded). 1 warp per query row.
// ---------------------------------------------------------------------------
__global__ void __launch_bounds__(256) attn_naive_kernel()
{
    const int lane = threadIdx.x & 31;
    const int warp = threadIdx.x >> 5;
    const int bh   = blockIdx.y;
    const int b    = bh >> 4;
    const int h    = bh & 15;
    const int q    = blockIdx.x * 8 + warp;

    const float* qb = g_qp + (size_t)(b * SEQ + q) * DIM + h * HD;
    const float* kb = g_kp + (size_t)b * SEQ * DIM + h * HD;
    const float* vb = g_vp + (size_t)b * SEQ * DIM + h * HD;

    const float q1 = qb[lane]      * 0.125f;   // 1/sqrt(64)
    const float q2 = qb[lane + 32] * 0.125f;

    float m = -1e30f, l = 0.0f, o1 = 0.0f, o2 = 0.0f;
    for (int k = 0; k <= q; k++) {
        float s = q1 * kb[(size_t)k * DIM + lane]
                + q2 * kb[(size_t)k * DIM + lane + 32];
#pragma unroll
        for (int off = 16; off; off >>= 1)
            s += __shfl_xor_sync(0xffffffffu, s, off);
        float mn   = fmaxf(m, s);
        float corr = __expf(m - mn);
        float p    = __expf(s - mn);
        m  = mn;
        l  = l * corr + p;
        o1 = o1 * corr + p * vb[(size_t)k * DIM + lane];
        o2 = o2 * corr + p * vb[(size_t)k * DIM + lane + 32];
    }

    float inv = 1.0f / l;
    float* op = g_ao + (size_t)(b * SEQ + q) * DIM + h * HD;
    op[lane]      = o1 * inv;
    op[lane + 32] = o2 * inv;
}

// ---------------------------------------------------------------------------
extern "C" void kernel_launch(void* const* d_in, const int* in_sizes, int n_in,
                              void* d_out, int out_size)
{
    // dict order: Q,K,V,Wq,Wk,Wv,Wo,bq,bk,bv,bo,mask (mask never dereferenced)
    const float* Q  = (const float*)d_in[0];
    const float* K  = (const float*)d_in[1];
    const float* V  = (const float*)d_in[2];
    const float* Wq = (const float*)d_in[3];
    const float* Wk = (const float*)d_in[4];
    const float* Wv = (const float*)d_in[5];
    const float* Wo = (const float*)d_in[6];
    const float* bq = (const float*)d_in[7];
    const float* bk = (const float*)d_in[8];
    const float* bv = (const float*)d_in[9];
    const float* bo = (const float*)d_in[10];
    float* out = (float*)d_out;

    const int gemm_blocks = (MROWS * DIM) / 256;   // 16384
    gemm_q_kernel<<<gemm_blocks, 256>>>(Q, Wq, bq);
    gemm_k_kernel<<<gemm_blocks, 256>>>(K, Wk, bk);
    gemm_v_kernel<<<gemm_blocks, 256>>>(V, Wv, bv);
    rope_kernel<<<(MROWS * (DIM / 2)) / 256, 256>>>();
    attn_naive_kernel<<<dim3(SEQ / 8, BATCH * HEADS), 256>>>();
    gemm_o_kernel<<<gemm_blocks, 256>>>(Wo, bo, out);
}

// round 8
// speedup vs baseline: 4.3228x; 4.3228x over previous
#include <cuda_runtime.h>
#include <math.h>

#define BATCH 2
#define SEQ   2048
#define DIM   1024
#define HEADS 16
#define HD    64
#define MROWS (BATCH*SEQ)   // 4096

// Scratch. Referenced ONLY from device code.
__device__ float g_qp[MROWS*DIM];
__device__ float g_kp[MROWS*DIM];
__device__ float g_vp[MROWS*DIM];
__device__ float g_ao[MROWS*DIM];

// ---------------------------------------------------------------------------
// Tiled GEMM: C[M,N] = A[M,K] @ W[K,N] + bias[N];  M=4096, N=K=1024
// 128x128 block tile, BK=16, 256 threads, 8x8 per thread.
// (Verified: produced bit-identical results to the naive GEMM in R1-R3/R6.)
// ---------------------------------------------------------------------------
__device__ __forceinline__ void gemm_body(const float* __restrict__ A,
                                          const float* __restrict__ W,
                                          const float* __restrict__ bias,
                                          float* __restrict__ C)
{
    __shared__ float As[16][128];   // As[k][m]
    __shared__ float Bs[16][128];   // Bs[k][n]

    const int tid  = threadIdx.x;
    const int tx   = tid & 15;
    const int ty   = tid >> 4;
    const int row0 = blockIdx.y * 128;
    const int col0 = blockIdx.x * 128;

    float acc[8][8];
#pragma unroll
    for (int i = 0; i < 8; i++)
#pragma unroll
        for (int j = 0; j < 8; j++) acc[i][j] = 0.0f;

    const int ar  = tid >> 2;
    const int ac4 = (tid & 3) * 4;
    const int br  = tid >> 5;
    const int bc4 = (tid & 31) * 4;

    for (int k0 = 0; k0 < DIM; k0 += 16) {
        float4 a0 = *(const float4*)(A + (size_t)(row0 + ar)      * DIM + k0 + ac4);
        float4 a1 = *(const float4*)(A + (size_t)(row0 + ar + 64) * DIM + k0 + ac4);
        float4 b0 = *(const float4*)(W + (size_t)(k0 + br)     * DIM + col0 + bc4);
        float4 b1 = *(const float4*)(W + (size_t)(k0 + br + 8) * DIM + col0 + bc4);

        As[ac4 + 0][ar]      = a0.x;  As[ac4 + 1][ar]      = a0.y;
        As[ac4 + 2][ar]      = a0.z;  As[ac4 + 3][ar]      = a0.w;
        As[ac4 + 0][ar + 64] = a1.x;  As[ac4 + 1][ar + 64] = a1.y;
        As[ac4 + 2][ar + 64] = a1.z;  As[ac4 + 3][ar + 64] = a1.w;
        *(float4*)&Bs[br][bc4]     = b0;
        *(float4*)&Bs[br + 8][bc4] = b1;
        __syncthreads();

#pragma unroll
        for (int kk = 0; kk < 16; kk++) {
            float4 x0 = *(float4*)&As[kk][ty * 8];
            float4 x1 = *(float4*)&As[kk][ty * 8 + 4];
            float4 y0 = *(float4*)&Bs[kk][tx * 8];
            float4 y1 = *(float4*)&Bs[kk][tx * 8 + 4];
            float av[8] = {x0.x, x0.y, x0.z, x0.w, x1.x, x1.y, x1.z, x1.w};
            float bv[8] = {y0.x, y0.y, y0.z, y0.w, y1.x, y1.y, y1.z, y1.w};
#pragma unroll
            for (int i = 0; i < 8; i++)
#pragma unroll
                for (int j = 0; j < 8; j++)
                    acc[i][j] += av[i] * bv[j];
        }
        __syncthreads();
    }

    float bb[8];
#pragma unroll
    for (int j = 0; j < 8; j++) bb[j] = bias[col0 + tx * 8 + j];

#pragma unroll
    for (int i = 0; i < 8; i++) {
        float4 o0 = make_float4(acc[i][0] + bb[0], acc[i][1] + bb[1],
                                acc[i][2] + bb[2], acc[i][3] + bb[3]);
        float4 o1 = make_float4(acc[i][4] + bb[4], acc[i][5] + bb[5],
                                acc[i][6] + bb[6], acc[i][7] + bb[7]);
        float* cp = C + (size_t)(row0 + ty * 8 + i) * DIM + col0 + tx * 8;
        *(float4*)cp       = o0;
        *(float4*)(cp + 4) = o1;
    }
}

__global__ void __launch_bounds__(256) gemm_q_kernel(const float* A, const float* W, const float* b) { gemm_body(A, W, b, g_qp); }
__global__ void __launch_bounds__(256) gemm_k_kernel(const float* A, const float* W, const float* b) { gemm_body(A, W, b, g_kp); }
__global__ void __launch_bounds__(256) gemm_v_kernel(const float* A, const float* W, const float* b) { gemm_body(A, W, b, g_vp); }
__global__ void __launch_bounds__(256) gemm_o_kernel(const float* W, const float* b, float* C)       { gemm_body(g_ao, W, b, C); }

// ---------------------------------------------------------------------------
// RoPE, CORRECTED direction (this is what passes):
// out1 = x1*cos + x2*sin;  out2 = x2*cos - x1*sin;  angle = pos * 10000^(-d/32)
// ---------------------------------------------------------------------------
__global__ void __launch_bounds__(256) rope_kernel()
{
    int idx = blockIdx.x * blockDim.x + threadIdx.x;
    if (idx >= MROWS * (DIM / 2)) return;
    int m = idx >> 9;
    int c = idx & 511;
    int h = c >> 5;
    int d = c & 31;
    int pos = m & (SEQ - 1);

    float invf = 1.0f / powf(10000.0f, (float)d * (1.0f / 32.0f));
    float ang  = (float)pos * invf;
    float cs, sn;
    sincosf(ang, &cs, &sn);

    int base = m * DIM + h * HD + d;
    float q1 = g_qp[base], q2 = g_qp[base + 32];
    g_qp[base]      = q1 * cs + q2 * sn;
    g_qp[base + 32] = q2 * cs - q1 * sn;
    float k1 = g_kp[base], k2 = g_kp[base + 32];
    g_kp[base]      = k1 * cs + k2 * sn;
    g_kp[base + 32] = k2 * cs - k1 * sn;
}

// ---------------------------------------------------------------------------
// Causal flash attention, 64x64 tiles. Grid: (SEQ/64, BATCH*HEADS).
// 256 threads (16x16), 4x4 per thread. Smem 48KB.
// (Verified vs warp-streaming version: bit-identical outputs.)
// ---------------------------------------------------------------------------
__global__ void __launch_bounds__(256) attn_kernel()
{
    __shared__ float Qst[64][64];   // [d][q]
    __shared__ float KPs[64][64];   // K phase: [d][k];  P phase: [k][q]
    __shared__ float Vs[64][64];    // [k][d]

    const int tid = threadIdx.x;
    const int tx  = tid & 15;
    const int ty  = tid >> 4;
    const int qt  = blockIdx.x;
    const int bh  = blockIdx.y;
    const int b   = bh >> 4;
    const int h   = bh & 15;
    const int q0  = qt * 64;
    const size_t headoff = (size_t)h * HD;

    // Load Q tile transposed, pre-scaled by 1/8
#pragma unroll
    for (int i = 0; i < 4; i++) {
        int idx = tid + i * 256;
        int r   = idx >> 4;
        int c4  = (idx & 15) * 4;
        float4 v = *(const float4*)(g_qp + (size_t)(b * SEQ + q0 + r) * DIM + headoff + c4);
        Qst[c4 + 0][r] = v.x * 0.125f;
        Qst[c4 + 1][r] = v.y * 0.125f;
        Qst[c4 + 2][r] = v.z * 0.125f;
        Qst[c4 + 3][r] = v.w * 0.125f;
    }

    float acc[4][4];
    float mrow[4], lrow[4];
#pragma unroll
    for (int i = 0; i < 4; i++) {
        mrow[i] = -1e30f;
        lrow[i] = 0.0f;
#pragma unroll
        for (int j = 0; j < 4; j++) acc[i][j] = 0.0f;
    }

    for (int jt = 0; jt <= qt; jt++) {
        const int k0 = jt * 64;
#pragma unroll
        for (int i = 0; i < 4; i++) {
            int idx = tid + i * 256;
            int r   = idx >> 4;
            int c4  = (idx & 15) * 4;
            size_t g = (size_t)(b * SEQ + k0 + r) * DIM + headoff + c4;
            float4 kv = *(const float4*)(g_kp + g);
            KPs[c4 + 0][r] = kv.x;  KPs[c4 + 1][r] = kv.y;
            KPs[c4 + 2][r] = kv.z;  KPs[c4 + 3][r] = kv.w;
            *(float4*)&Vs[r][c4] = *(const float4*)(g_vp + g);
        }
        __syncthreads();

        // S = Q @ K^T
        float s[4][4];
#pragma unroll
        for (int i = 0; i < 4; i++)
#pragma unroll
            for (int j = 0; j < 4; j++) s[i][j] = 0.0f;

#pragma unroll 16
        for (int d = 0; d < 64; d++) {
            float4 a = *(float4*)&Qst[d][ty * 4];
            float4 c = *(float4*)&KPs[d][tx * 4];
            float av[4] = {a.x, a.y, a.z, a.w};
            float cv[4] = {c.x, c.y, c.z, c.w};
#pragma unroll
            for (int i = 0; i < 4; i++)
#pragma unroll
                for (int j = 0; j < 4; j++)
                    s[i][j] += av[i] * cv[j];
        }

        if (jt == qt) {
#pragma unroll
            for (int i = 0; i < 4; i++)
#pragma unroll
                for (int j = 0; j < 4; j++)
                    if (tx * 4 + j > ty * 4 + i) s[i][j] = -1e30f;
        }

        // Online softmax per row (reduce over the 16 tx lanes sharing ty)
#pragma unroll
        for (int i = 0; i < 4; i++) {
            float mx = fmaxf(fmaxf(s[i][0], s[i][1]), fmaxf(s[i][2], s[i][3]));
#pragma unroll
            for (int o = 8; o; o >>= 1)
                mx = fmaxf(mx, __shfl_xor_sync(0xffffffffu, mx, o));
            float mn   = fmaxf(mrow[i], mx);
            float corr = __expf(mrow[i] - mn);
            mrow[i]    = mn;
            float rs = 0.0f;
#pragma unroll
            for (int j = 0; j < 4; j++) {
                s[i][j] = __expf(s[i][j] - mn);
                rs += s[i][j];
            }
#pragma unroll
            for (int o = 8; o; o >>= 1)
                rs += __shfl_xor_sync(0xffffffffu, rs, o);
            lrow[i] = lrow[i] * corr + rs;
#pragma unroll
            for (int j = 0; j < 4; j++) acc[i][j] *= corr;
        }
        __syncthreads();

        // P^T into KPs
#pragma unroll
        for (int i = 0; i < 4; i++)
#pragma unroll
            for (int j = 0; j < 4; j++)
                KPs[tx * 4 + j][ty * 4 + i] = s[i][j];
        __syncthreads();

        // O += P @ V
#pragma unroll 16
        for (int k = 0; k < 64; k++) {
            float4 a = *(float4*)&KPs[k][ty * 4];
            float4 v = *(float4*)&Vs[k][tx * 4];
            float av[4] = {a.x, a.y, a.z, a.w};
            float vv[4] = {v.x, v.y, v.z, v.w};
#pragma unroll
            for (int i = 0; i < 4; i++)
#pragma unroll
                for (int j = 0; j < 4; j++)
                    acc[i][j] += av[i] * vv[j];
        }
        __syncthreads();
    }

#pragma unroll
    for (int i = 0; i < 4; i++) {
        float inv = 1.0f / lrow[i];
        float4 o = make_float4(acc[i][0] * inv, acc[i][1] * inv,
                               acc[i][2] * inv, acc[i][3] * inv);
        *(float4*)(g_ao + (size_t)(b * SEQ + q0 + ty * 4 + i) * DIM + headoff + tx * 4) = o;
    }
}

// ---------------------------------------------------------------------------
extern "C" void kernel_launch(void* const* d_in, const int* in_sizes, int n_in,
                              void* d_out, int out_size)
{
    const float* Q  = (const float*)d_in[0];
    const float* K  = (const float*)d_in[1];
    const float* V  = (const float*)d_in[2];
    const float* Wq = (const float*)d_in[3];
    const float* Wk = (const float*)d_in[4];
    const float* Wv = (const float*)d_in[5];
    const float* Wo = (const float*)d_in[6];
    const float* bq = (const float*)d_in[7];
    const float* bk = (const float*)d_in[8];
    const float* bv = (const float*)d_in[9];
    const float* bo = (const float*)d_in[10];
    float* out = (float*)d_out;

    dim3 gg(DIM / 128, MROWS / 128);   // (8, 32)
    gemm_q_kernel<<<gg, 256>>>(Q, Wq, bq);
    gemm_k_kernel<<<gg, 256>>>(K, Wk, bk);
    gemm_v_kernel<<<gg, 256>>>(V, Wv, bv);
    rope_kernel<<<(MROWS * (DIM / 2)) / 256, 256>>>();
    attn_kernel<<<dim3(SEQ / 64, BATCH * HEADS), 256>>>();
    gemm_o_kernel<<<gg, 256>>>(Wo, bo, out);
}

// round 9
// speedup vs baseline: 6.3691x; 1.4734x over previous
#include <cuda_runtime.h>
#include <math.h>

#define BATCH 2
#define SEQ   2048
#define DIM   1024
#define HEADS 16
#define HD    64
#define MROWS (BATCH*SEQ)   // 4096

// Scratch. Referenced ONLY from device code.
__device__ float g_qp[MROWS*DIM];
__device__ float g_kp[MROWS*DIM];
__device__ float g_vp[MROWS*DIM];
__device__ float g_ao[MROWS*DIM];

// ---------------------------------------------------------------------------
// tf32 helpers
// ---------------------------------------------------------------------------
__device__ __forceinline__ unsigned f2tf32(float x) {
    unsigned r;
    asm("cvt.rna.tf32.f32 %0, %1;" : "=r"(r) : "f"(x));
    return r;
}

__device__ __forceinline__ void mma_tf32(float d[4], const unsigned a[4],
                                         const unsigned b[2], const float c[4]) {
    asm volatile(
        "mma.sync.aligned.m16n8k8.row.col.f32.tf32.tf32.f32 "
        "{%0,%1,%2,%3}, {%4,%5,%6,%7}, {%8,%9}, {%10,%11,%12,%13};"
        : "=f"(d[0]), "=f"(d[1]), "=f"(d[2]), "=f"(d[3])
        : "r"(a[0]), "r"(a[1]), "r"(a[2]), "r"(a[3]),
          "r"(b[0]), "r"(b[1]),
          "f"(c[0]), "f"(c[1]), "f"(c[2]), "f"(c[3]));
}

// ---------------------------------------------------------------------------
// tf32 tensor-core GEMM: C[M,N] = A[M,K] @ W[K,N] + bias[N]
// Block tile 128x128, BK=32, 256 threads = 8 warps (2x4), warp tile 64x32.
// Each warp: 4x4 grid of m16n8k8 mma; fp32 accumulate; RNA tf32 rounding.
// ---------------------------------------------------------------------------
__device__ __forceinline__ void gemm_tf32_body(const float* __restrict__ A,
                                               const float* __restrict__ W,
                                               const float* __restrict__ bias,
                                               float* __restrict__ C)
{
    __shared__ unsigned As[128][36];   // [m][k], pad 36: LDS bank = 4r+c (unique)
    __shared__ unsigned Bs[32][132];   // [k][n], pad 132: LDS bank = 4c+r (unique)

    const int tid  = threadIdx.x;
    const int lane = tid & 31;
    const int warp = tid >> 5;
    const int wm   = warp >> 2;        // 0..1
    const int wn   = warp & 3;         // 0..3
    const int r    = lane >> 2;        // group id 0..7
    const int c    = lane & 3;         // thread-in-group 0..3
    const int row0 = blockIdx.y * 128;
    const int col0 = blockIdx.x * 128;

    float acc[4][4][4];
#pragma unroll
    for (int mt = 0; mt < 4; mt++)
#pragma unroll
        for (int nt = 0; nt < 4; nt++)
#pragma unroll
            for (int e = 0; e < 4; e++) acc[mt][nt][e] = 0.0f;

    for (int k0 = 0; k0 < DIM; k0 += 32) {
        // Stage A tile: 128 rows x 32 k, float4 loads, tf32 convert
#pragma unroll
        for (int i = 0; i < 4; i++) {
            int idx = tid + i * 256;           // 0..1023
            int ar  = idx >> 3;                // row 0..127
            int ac4 = (idx & 7) << 2;          // k 0,4,..28
            float4 v = *(const float4*)(A + (size_t)(row0 + ar) * DIM + k0 + ac4);
            uint4 t = make_uint4(f2tf32(v.x), f2tf32(v.y), f2tf32(v.z), f2tf32(v.w));
            *(uint4*)&As[ar][ac4] = t;         // 144B row stride -> 16B aligned
        }
        // Stage B tile: 32 k x 128 n
#pragma unroll
        for (int i = 0; i < 4; i++) {
            int idx = tid + i * 256;
            int br  = idx >> 5;                // k 0..31
            int bc4 = (idx & 31) << 2;         // n 0,4,..124
            float4 v = *(const float4*)(W + (size_t)(k0 + br) * DIM + col0 + bc4);
            uint4 t = make_uint4(f2tf32(v.x), f2tf32(v.y), f2tf32(v.z), f2tf32(v.w));
            *(uint4*)&Bs[br][bc4] = t;         // 528B row stride -> 16B aligned
        }
        __syncthreads();

#pragma unroll
        for (int ks = 0; ks < 4; ks++) {
            const int kk = ks * 8;
            unsigned a[4][4], b[4][2];
#pragma unroll
            for (int mt = 0; mt < 4; mt++) {
                int m = wm * 64 + mt * 16;
                a[mt][0] = As[m + r    ][kk + c    ];
                a[mt][1] = As[m + r + 8][kk + c    ];
                a[mt][2] = As[m + r    ][kk + c + 4];
                a[mt][3] = As[m + r + 8][kk + c + 4];
            }
#pragma unroll
            for (int nt = 0; nt < 4; nt++) {
                int n = wn * 32 + nt * 8 + r;
                b[nt][0] = Bs[kk + c    ][n];
                b[nt][1] = Bs[kk + c + 4][n];
            }
#pragma unroll
            for (int mt = 0; mt < 4; mt++)
#pragma unroll
                for (int nt = 0; nt < 4; nt++)
                    mma_tf32(acc[mt][nt], a[mt], b[nt], acc[mt][nt]);
        }
        __syncthreads();
    }

    // Epilogue: d0 (r, 2c), d1 (r, 2c+1), d2 (r+8, 2c), d3 (r+8, 2c+1)
#pragma unroll
    for (int nt = 0; nt < 4; nt++) {
        int col = col0 + wn * 32 + nt * 8 + 2 * c;
        float b0 = bias[col], b1 = bias[col + 1];
#pragma unroll
        for (int mt = 0; mt < 4; mt++) {
            int row = row0 + wm * 64 + mt * 16 + r;
            float2 lo = make_float2(acc[mt][nt][0] + b0, acc[mt][nt][1] + b1);
            float2 hi = make_float2(acc[mt][nt][2] + b0, acc[mt][nt][3] + b1);
            *(float2*)(C + (size_t)row * DIM + col)       = lo;
            *(float2*)(C + (size_t)(row + 8) * DIM + col) = hi;
        }
    }
}

__global__ void __launch_bounds__(256) gemm_q_kernel(const float* A, const float* W, const float* b) { gemm_tf32_body(A, W, b, g_qp); }
__global__ void __launch_bounds__(256) gemm_k_kernel(const float* A, const float* W, const float* b) { gemm_tf32_body(A, W, b, g_kp); }
__global__ void __launch_bounds__(256) gemm_v_kernel(const float* A, const float* W, const float* b) { gemm_tf32_body(A, W, b, g_vp); }
__global__ void __launch_bounds__(256) gemm_o_kernel(const float* W, const float* b, float* C)       { gemm_tf32_body(g_ao, W, b, C); }

// ---------------------------------------------------------------------------
// RoPE, corrected direction:
// out1 = x1*cos + x2*sin;  out2 = x2*cos - x1*sin;  angle = pos * 10000^(-d/32)
// ---------------------------------------------------------------------------
__global__ void __launch_bounds__(256) rope_kernel()
{
    int idx = blockIdx.x * blockDim.x + threadIdx.x;
    if (idx >= MROWS * (DIM / 2)) return;
    int m = idx >> 9;
    int cc = idx & 511;
    int h = cc >> 5;
    int d = cc & 31;
    int pos = m & (SEQ - 1);

    float invf = 1.0f / powf(10000.0f, (float)d * (1.0f / 32.0f));
    float ang  = (float)pos * invf;
    float cs, sn;
    sincosf(ang, &cs, &sn);

    int base = m * DIM + h * HD + d;
    float q1 = g_qp[base], q2 = g_qp[base + 32];
    g_qp[base]      = q1 * cs + q2 * sn;
    g_qp[base + 32] = q2 * cs - q1 * sn;
    float k1 = g_kp[base], k2 = g_kp[base + 32];
    g_kp[base]      = k1 * cs + k2 * sn;
    g_kp[base + 32] = k2 * cs - k1 * sn;
}

// ---------------------------------------------------------------------------
// Causal flash attention, 64x64 tiles, fp32 SIMT (verified).
// ---------------------------------------------------------------------------
__global__ void __launch_bounds__(256) attn_kernel()
{
    __shared__ float Qst[64][64];
    __shared__ float KPs[64][64];
    __shared__ float Vs[64][64];

    const int tid = threadIdx.x;
    const int tx  = tid & 15;
    const int ty  = tid >> 4;
    const int qt  = blockIdx.x;
    const int bh  = blockIdx.y;
    const int b   = bh >> 4;
    const int h   = bh & 15;
    const int q0  = qt * 64;
    const size_t headoff = (size_t)h * HD;

#pragma unroll
    for (int i = 0; i < 4; i++) {
        int idx = tid + i * 256;
        int r   = idx >> 4;
        int c4  = (idx & 15) * 4;
        float4 v = *(const float4*)(g_qp + (size_t)(b * SEQ + q0 + r) * DIM + headoff + c4);
        Qst[c4 + 0][r] = v.x * 0.125f;
        Qst[c4 + 1][r] = v.y * 0.125f;
        Qst[c4 + 2][r] = v.z * 0.125f;
        Qst[c4 + 3][r] = v.w * 0.125f;
    }

    float acc[4][4];
    float mrow[4], lrow[4];
#pragma unroll
    for (int i = 0; i < 4; i++) {
        mrow[i] = -1e30f;
        lrow[i] = 0.0f;
#pragma unroll
        for (int j = 0; j < 4; j++) acc[i][j] = 0.0f;
    }

    for (int jt = 0; jt <= qt; jt++) {
        const int k0 = jt * 64;
#pragma unroll
        for (int i = 0; i < 4; i++) {
            int idx = tid + i * 256;
            int r   = idx >> 4;
            int c4  = (idx & 15) * 4;
            size_t g = (size_t)(b * SEQ + k0 + r) * DIM + headoff + c4;
            float4 kv = *(const float4*)(g_kp + g);
            KPs[c4 + 0][r] = kv.x;  KPs[c4 + 1][r] = kv.y;
            KPs[c4 + 2][r] = kv.z;  KPs[c4 + 3][r] = kv.w;
            *(float4*)&Vs[r][c4] = *(const float4*)(g_vp + g);
        }
        __syncthreads();

        float s[4][4];
#pragma unroll
        for (int i = 0; i < 4; i++)
#pragma unroll
            for (int j = 0; j < 4; j++) s[i][j] = 0.0f;

#pragma unroll 16
        for (int d = 0; d < 64; d++) {
            float4 a = *(float4*)&Qst[d][ty * 4];
            float4 cv4 = *(float4*)&KPs[d][tx * 4];
            float av[4] = {a.x, a.y, a.z, a.w};
            float cv[4] = {cv4.x, cv4.y, cv4.z, cv4.w};
#pragma unroll
            for (int i = 0; i < 4; i++)
#pragma unroll
                for (int j = 0; j < 4; j++)
                    s[i][j] += av[i] * cv[j];
        }

        if (jt == qt) {
#pragma unroll
            for (int i = 0; i < 4; i++)
#pragma unroll
                for (int j = 0; j < 4; j++)
                    if (tx * 4 + j > ty * 4 + i) s[i][j] = -1e30f;
        }

#pragma unroll
        for (int i = 0; i < 4; i++) {
            float mx = fmaxf(fmaxf(s[i][0], s[i][1]), fmaxf(s[i][2], s[i][3]));
#pragma unroll
            for (int o = 8; o; o >>= 1)
                mx = fmaxf(mx, __shfl_xor_sync(0xffffffffu, mx, o));
            float mn   = fmaxf(mrow[i], mx);
            float corr = __expf(mrow[i] - mn);
            mrow[i]    = mn;
            float rs = 0.0f;
#pragma unroll
            for (int j = 0; j < 4; j++) {
                s[i][j] = __expf(s[i][j] - mn);
                rs += s[i][j];
            }
#pragma unroll
            for (int o = 8; o; o >>= 1)
                rs += __shfl_xor_sync(0xffffffffu, rs, o);
            lrow[i] = lrow[i] * corr + rs;
#pragma unroll
            for (int j = 0; j < 4; j++) acc[i][j] *= corr;
        }
        __syncthreads();

#pragma unroll
        for (int i = 0; i < 4; i++)
#pragma unroll
            for (int j = 0; j < 4; j++)
                KPs[tx * 4 + j][ty * 4 + i] = s[i][j];
        __syncthreads();

#pragma unroll 16
        for (int k = 0; k < 64; k++) {
            float4 a = *(float4*)&KPs[k][ty * 4];
            float4 v = *(float4*)&Vs[k][tx * 4];
            float av[4] = {a.x, a.y, a.z, a.w};
            float vv[4] = {v.x, v.y, v.z, v.w};
#pragma unroll
            for (int i = 0; i < 4; i++)
#pragma unroll
                for (int j = 0; j < 4; j++)
                    acc[i][j] += av[i] * vv[j];
        }
        __syncthreads();
    }

#pragma unroll
    for (int i = 0; i < 4; i++) {
        float inv = 1.0f / lrow[i];
        float4 o = make_float4(acc[i][0] * inv, acc[i][1] * inv,
                               acc[i][2] * inv, acc[i][3] * inv);
        *(float4*)(g_ao + (size_t)(b * SEQ + q0 + ty * 4 + i) * DIM + headoff + tx * 4) = o;
    }
}

// ---------------------------------------------------------------------------
extern "C" void kernel_launch(void* const* d_in, const int* in_sizes, int n_in,
                              void* d_out, int out_size)
{
    const float* Q  = (const float*)d_in[0];
    const float* K  = (const float*)d_in[1];
    const float* V  = (const float*)d_in[2];
    const float* Wq = (const float*)d_in[3];
    const float* Wk = (const float*)d_in[4];
    const float* Wv = (const float*)d_in[5];
    const float* Wo = (const float*)d_in[6];
    const float* bq = (const float*)d_in[7];
    const float* bk = (const float*)d_in[8];
    const float* bv = (const float*)d_in[9];
    const float* bo = (const float*)d_in[10];
    float* out = (float*)d_out;

    dim3 gg(DIM / 128, MROWS / 128);   // (8, 32)
    gemm_q_kernel<<<gg, 256>>>(Q, Wq, bq);
    gemm_k_kernel<<<gg, 256>>>(K, Wk, bk);
    gemm_v_kernel<<<gg, 256>>>(V, Wv, bv);
    rope_kernel<<<(MROWS * (DIM / 2)) / 256, 256>>>();
    attn_kernel<<<dim3(SEQ / 64, BATCH * HEADS), 256>>>();
    gemm_o_kernel<<<gg, 256>>>(Wo, bo, out);
}

// round 10
// speedup vs baseline: 14.4702x; 2.2719x over previous
#include <cuda_runtime.h>
#include <math.h>

#define BATCH 2
#define SEQ   2048
#define DIM   1024
#define HEADS 16
#define HD    64
#define MROWS (BATCH*SEQ)   // 4096

// Scratch. Referenced ONLY from device code.
__device__ float g_qp[MROWS*DIM];
__device__ float g_kp[MROWS*DIM];
__device__ float g_vp[MROWS*DIM];
__device__ float g_ao[MROWS*DIM];

// ---------------------------------------------------------------------------
// tf32 helpers (fragment layouts validated in R9)
// ---------------------------------------------------------------------------
__device__ __forceinline__ unsigned f2tf32(float x) {
    unsigned r;
    asm("cvt.rna.tf32.f32 %0, %1;" : "=r"(r) : "f"(x));
    return r;
}
__device__ __forceinline__ uint4 tf32x4(float4 v) {
    return make_uint4(f2tf32(v.x), f2tf32(v.y), f2tf32(v.z), f2tf32(v.w));
}
__device__ __forceinline__ void mma_tf32(float d[4], const unsigned a[4],
                                         const unsigned b[2], const float c[4]) {
    asm volatile(
        "mma.sync.aligned.m16n8k8.row.col.f32.tf32.tf32.f32 "
        "{%0,%1,%2,%3}, {%4,%5,%6,%7}, {%8,%9}, {%10,%11,%12,%13};"
        : "=f"(d[0]), "=f"(d[1]), "=f"(d[2]), "=f"(d[3])
        : "r"(a[0]), "r"(a[1]), "r"(a[2]), "r"(a[3]),
          "r"(b[0]), "r"(b[1]),
          "f"(c[0]), "f"(c[1]), "f"(c[2]), "f"(c[3]));
}

// ---------------------------------------------------------------------------
// tf32 tensor-core GEMM (unchanged from R9, validated).
// ---------------------------------------------------------------------------
__device__ __forceinline__ void gemm_tf32_body(const float* __restrict__ A,
                                               const float* __restrict__ W,
                                               const float* __restrict__ bias,
                                               float* __restrict__ C)
{
    __shared__ unsigned As[128][36];
    __shared__ unsigned Bs[32][132];

    const int tid  = threadIdx.x;
    const int lane = tid & 31;
    const int warp = tid >> 5;
    const int wm   = warp >> 2;
    const int wn   = warp & 3;
    const int r    = lane >> 2;
    const int c    = lane & 3;
    const int row0 = blockIdx.y * 128;
    const int col0 = blockIdx.x * 128;

    float acc[4][4][4];
#pragma unroll
    for (int mt = 0; mt < 4; mt++)
#pragma unroll
        for (int nt = 0; nt < 4; nt++)
#pragma unroll
            for (int e = 0; e < 4; e++) acc[mt][nt][e] = 0.0f;

    for (int k0 = 0; k0 < DIM; k0 += 32) {
#pragma unroll
        for (int i = 0; i < 4; i++) {
            int idx = tid + i * 256;
            int ar  = idx >> 3;
            int ac4 = (idx & 7) << 2;
            float4 v = *(const float4*)(A + (size_t)(row0 + ar) * DIM + k0 + ac4);
            *(uint4*)&As[ar][ac4] = tf32x4(v);
        }
#pragma unroll
        for (int i = 0; i < 4; i++) {
            int idx = tid + i * 256;
            int br  = idx >> 5;
            int bc4 = (idx & 31) << 2;
            float4 v = *(const float4*)(W + (size_t)(k0 + br) * DIM + col0 + bc4);
            *(uint4*)&Bs[br][bc4] = tf32x4(v);
        }
        __syncthreads();

#pragma unroll
        for (int ks = 0; ks < 4; ks++) {
            const int kk = ks * 8;
            unsigned a[4][4], b[4][2];
#pragma unroll
            for (int mt = 0; mt < 4; mt++) {
                int m = wm * 64 + mt * 16;
                a[mt][0] = As[m + r    ][kk + c    ];
                a[mt][1] = As[m + r + 8][kk + c    ];
                a[mt][2] = As[m + r    ][kk + c + 4];
                a[mt][3] = As[m + r + 8][kk + c + 4];
            }
#pragma unroll
            for (int nt = 0; nt < 4; nt++) {
                int n = wn * 32 + nt * 8 + r;
                b[nt][0] = Bs[kk + c    ][n];
                b[nt][1] = Bs[kk + c + 4][n];
            }
#pragma unroll
            for (int mt = 0; mt < 4; mt++)
#pragma unroll
                for (int nt = 0; nt < 4; nt++)
                    mma_tf32(acc[mt][nt], a[mt], b[nt], acc[mt][nt]);
        }
        __syncthreads();
    }

#pragma unroll
    for (int nt = 0; nt < 4; nt++) {
        int col = col0 + wn * 32 + nt * 8 + 2 * c;
        float b0 = bias[col], b1 = bias[col + 1];
#pragma unroll
        for (int mt = 0; mt < 4; mt++) {
            int row = row0 + wm * 64 + mt * 16 + r;
            float2 lo = make_float2(acc[mt][nt][0] + b0, acc[mt][nt][1] + b1);
            float2 hi = make_float2(acc[mt][nt][2] + b0, acc[mt][nt][3] + b1);
            *(float2*)(C + (size_t)row * DIM + col)       = lo;
            *(float2*)(C + (size_t)(row + 8) * DIM + col) = hi;
        }
    }
}

__global__ void __launch_bounds__(256) gemm_q_kernel(const float* A, const float* W, const float* b) { gemm_tf32_body(A, W, b, g_qp); }
__global__ void __launch_bounds__(256) gemm_k_kernel(const float* A, const float* W, const float* b) { gemm_tf32_body(A, W, b, g_kp); }
__global__ void __launch_bounds__(256) gemm_v_kernel(const float* A, const float* W, const float* b) { gemm_tf32_body(A, W, b, g_vp); }
__global__ void __launch_bounds__(256) gemm_o_kernel(const float* W, const float* b, float* C)       { gemm_tf32_body(g_ao, W, b, C); }

// ---------------------------------------------------------------------------
// RoPE (corrected direction, validated).
// ---------------------------------------------------------------------------
__global__ void __launch_bounds__(256) rope_kernel()
{
    int idx = blockIdx.x * blockDim.x + threadIdx.x;
    if (idx >= MROWS * (DIM / 2)) return;
    int m = idx >> 9;
    int cc = idx & 511;
    int h = cc >> 5;
    int d = cc & 31;
    int pos = m & (SEQ - 1);

    float invf = 1.0f / powf(10000.0f, (float)d * (1.0f / 32.0f));
    float ang  = (float)pos * invf;
    float cs, sn;
    sincosf(ang, &cs, &sn);

    int base = m * DIM + h * HD + d;
    float q1 = g_qp[base], q2 = g_qp[base + 32];
    g_qp[base]      = q1 * cs + q2 * sn;
    g_qp[base + 32] = q2 * cs - q1 * sn;
    float k1 = g_kp[base], k2 = g_kp[base + 32];
    g_kp[base]      = k1 * cs + k2 * sn;
    g_kp[base + 32] = k2 * cs - k1 * sn;
}

// ---------------------------------------------------------------------------
// tf32 tensor-core causal flash attention.
// Grid (SEQ/64, BATCH*HEADS); 128 threads = 4 warps; warp owns 16 q-rows.
// Dynamic smem: Qs[64][68], Ks[64][68], Vs[64][72], Ps[64][68] (tf32 bits).
// Pads: 68 -> A/B frag bank = 4r+c (unique); Vs 72 -> B frag bank = 8c+r.
// ---------------------------------------------------------------------------
#define SM_QS 0
#define SM_KS 4352          // 64*68
#define SM_VS 8704          // + 64*68
#define SM_PS 13312         // + 64*72
#define SM_TOTAL_U32 17664  // + 64*68
#define SM_TOTAL_BYTES (SM_TOTAL_U32*4)

__global__ void __launch_bounds__(128) attn_kernel()
{
    extern __shared__ unsigned sm[];
    unsigned (*Qs)[68] = (unsigned(*)[68])(sm + SM_QS);
    unsigned (*Ks)[68] = (unsigned(*)[68])(sm + SM_KS);
    unsigned (*Vs)[72] = (unsigned(*)[72])(sm + SM_VS);
    unsigned (*Ps)[68] = (unsigned(*)[68])(sm + SM_PS);

    const int tid  = threadIdx.x;
    const int lane = tid & 31;
    const int warp = tid >> 5;        // 0..3
    const int r    = lane >> 2;       // 0..7
    const int c    = lane & 3;        // 0..3
    const int w16  = warp * 16;
    const int qt   = blockIdx.x;
    const int bh   = blockIdx.y;
    const int b    = bh >> 4;
    const int h    = bh & 15;
    const int q0   = qt * 64;
    const size_t headoff = (size_t)h * HD;

    // Stage Q tile (scaled by 1/8 — exact power of 2 — then tf32)
#pragma unroll
    for (int i = 0; i < 8; i++) {
        int idx = tid + i * 128;
        int rr  = idx >> 4;
        int c4  = (idx & 15) * 4;
        float4 v = *(const float4*)(g_qp + (size_t)(b * SEQ + q0 + rr) * DIM + headoff + c4);
        v.x *= 0.125f; v.y *= 0.125f; v.z *= 0.125f; v.w *= 0.125f;
        *(uint4*)&Qs[rr][c4] = tf32x4(v);
    }

    float o[8][4];
#pragma unroll
    for (int nt = 0; nt < 8; nt++)
#pragma unroll
        for (int e = 0; e < 4; e++) o[nt][e] = 0.0f;
    float m_a = -1e30f, m_b = -1e30f, l_a = 0.0f, l_b = 0.0f;

    for (int jt = 0; jt <= qt; jt++) {
        const int k0 = jt * 64;
        __syncthreads();   // prev iter's mma reads done; Q staging visible (iter 0)
#pragma unroll
        for (int i = 0; i < 8; i++) {
            int idx = tid + i * 128;
            int rr  = idx >> 4;
            int c4  = (idx & 15) * 4;
            size_t g = (size_t)(b * SEQ + k0 + rr) * DIM + headoff + c4;
            *(uint4*)&Ks[rr][c4] = tf32x4(*(const float4*)(g_kp + g));
            *(uint4*)&Vs[rr][c4] = tf32x4(*(const float4*)(g_vp + g));
        }
        __syncthreads();

        // S = Q @ K^T : warp computes 16x64 via 8x8 mma grid
        float s[8][4];
#pragma unroll
        for (int nt = 0; nt < 8; nt++)
#pragma unroll
            for (int e = 0; e < 4; e++) s[nt][e] = 0.0f;

#pragma unroll
        for (int ks = 0; ks < 8; ks++) {
            const int kk = ks * 8;
            unsigned a[4] = { Qs[w16 + r    ][kk + c    ],
                              Qs[w16 + r + 8][kk + c    ],
                              Qs[w16 + r    ][kk + c + 4],
                              Qs[w16 + r + 8][kk + c + 4] };
#pragma unroll
            for (int nt = 0; nt < 8; nt++) {
                unsigned bf[2] = { Ks[nt * 8 + r][kk + c    ],
                                   Ks[nt * 8 + r][kk + c + 4] };
                mma_tf32(s[nt], a, bf, s[nt]);
            }
        }

        // Causal mask on the diagonal tile (local indices; k0 == q0)
        if (jt == qt) {
            const int ra = w16 + r, rb = ra + 8;
#pragma unroll
            for (int nt = 0; nt < 8; nt++) {
                int c0_ = nt * 8 + 2 * c;
                if (c0_     > ra) s[nt][0] = -1e30f;
                if (c0_ + 1 > ra) s[nt][1] = -1e30f;
                if (c0_     > rb) s[nt][2] = -1e30f;
                if (c0_ + 1 > rb) s[nt][3] = -1e30f;
            }
        }

        // Online softmax: rows (w16+r) [d0,d1] and (w16+r+8) [d2,d3];
        // row spread across quad lanes -> shfl xor 1,2.
        float mxa = -1e30f, mxb = -1e30f;
#pragma unroll
        for (int nt = 0; nt < 8; nt++) {
            mxa = fmaxf(mxa, fmaxf(s[nt][0], s[nt][1]));
            mxb = fmaxf(mxb, fmaxf(s[nt][2], s[nt][3]));
        }
        mxa = fmaxf(mxa, __shfl_xor_sync(0xffffffffu, mxa, 1));
        mxa = fmaxf(mxa, __shfl_xor_sync(0xffffffffu, mxa, 2));
        mxb = fmaxf(mxb, __shfl_xor_sync(0xffffffffu, mxb, 1));
        mxb = fmaxf(mxb, __shfl_xor_sync(0xffffffffu, mxb, 2));

        float mna = fmaxf(m_a, mxa), mnb = fmaxf(m_b, mxb);
        float corra = __expf(m_a - mna), corrb = __expf(m_b - mnb);
        m_a = mna; m_b = mnb;

        float ra_ = 0.0f, rb_ = 0.0f;
#pragma unroll
        for (int nt = 0; nt < 8; nt++) {
            s[nt][0] = __expf(s[nt][0] - m_a);
            s[nt][1] = __expf(s[nt][1] - m_a);
            s[nt][2] = __expf(s[nt][2] - m_b);
            s[nt][3] = __expf(s[nt][3] - m_b);
            ra_ += s[nt][0] + s[nt][1];
            rb_ += s[nt][2] + s[nt][3];
        }
        ra_ += __shfl_xor_sync(0xffffffffu, ra_, 1);
        ra_ += __shfl_xor_sync(0xffffffffu, ra_, 2);
        rb_ += __shfl_xor_sync(0xffffffffu, rb_, 1);
        rb_ += __shfl_xor_sync(0xffffffffu, rb_, 2);
        l_a = l_a * corra + ra_;
        l_b = l_b * corrb + rb_;

#pragma unroll
        for (int nt = 0; nt < 8; nt++) {
            o[nt][0] *= corra; o[nt][1] *= corra;
            o[nt][2] *= corrb; o[nt][3] *= corrb;
        }

        // P -> tf32 -> smem (own warp rows only)
#pragma unroll
        for (int nt = 0; nt < 8; nt++) {
            *(uint2*)&Ps[w16 + r    ][nt * 8 + 2 * c] =
                make_uint2(f2tf32(s[nt][0]), f2tf32(s[nt][1]));
            *(uint2*)&Ps[w16 + r + 8][nt * 8 + 2 * c] =
                make_uint2(f2tf32(s[nt][2]), f2tf32(s[nt][3]));
        }
        __syncwarp();

        // O += P @ V
#pragma unroll
        for (int ks = 0; ks < 8; ks++) {
            const int kk = ks * 8;
            unsigned a[4] = { Ps[w16 + r    ][kk + c    ],
                              Ps[w16 + r + 8][kk + c    ],
                              Ps[w16 + r    ][kk + c + 4],
                              Ps[w16 + r + 8][kk + c + 4] };
#pragma unroll
            for (int nt = 0; nt < 8; nt++) {
                unsigned bf[2] = { Vs[kk + c    ][nt * 8 + r],
                                   Vs[kk + c + 4][nt * 8 + r] };
                mma_tf32(o[nt], a, bf, o[nt]);
            }
        }
    }

    // Normalize and write
    float ia = 1.0f / l_a, ib = 1.0f / l_b;
    size_t rowa = (size_t)(b * SEQ + q0 + w16 + r) * DIM + headoff;
#pragma unroll
    for (int nt = 0; nt < 8; nt++) {
        int col = nt * 8 + 2 * c;
        *(float2*)(g_ao + rowa + col)             = make_float2(o[nt][0] * ia, o[nt][1] * ia);
        *(float2*)(g_ao + rowa + 8 * DIM + col)   = make_float2(o[nt][2] * ib, o[nt][3] * ib);
    }
}

// ---------------------------------------------------------------------------
extern "C" void kernel_launch(void* const* d_in, const int* in_sizes, int n_in,
                              void* d_out, int out_size)
{
    const float* Q  = (const float*)d_in[0];
    const float* K  = (const float*)d_in[1];
    const float* V  = (const float*)d_in[2];
    const float* Wq = (const float*)d_in[3];
    const float* Wk = (const float*)d_in[4];
    const float* Wv = (const float*)d_in[5];
    const float* Wo = (const float*)d_in[6];
    const float* bq = (const float*)d_in[7];
    const float* bk = (const float*)d_in[8];
    const float* bv = (const float*)d_in[9];
    const float* bo = (const float*)d_in[10];
    float* out = (float*)d_out;

    cudaFuncSetAttribute(attn_kernel, cudaFuncAttributeMaxDynamicSharedMemorySize,
                         SM_TOTAL_BYTES);

    dim3 gg(DIM / 128, MROWS / 128);   // (8, 32)
    gemm_q_kernel<<<gg, 256>>>(Q, Wq, bq);
    gemm_k_kernel<<<gg, 256>>>(K, Wk, bk);
    gemm_v_kernel<<<gg, 256>>>(V, Wv, bv);
    rope_kernel<<<(MROWS * (DIM / 2)) / 256, 256>>>();
    attn_kernel<<<dim3(SEQ / 64, BATCH * HEADS), 128, SM_TOTAL_BYTES>>>();
    gemm_o_kernel<<<gg, 256>>>(Wo, bo, out);
}

// round 11
// speedup vs baseline: 15.1350x; 1.0459x over previous
#include <cuda_runtime.h>
#include <math.h>

#define BATCH 2
#define SEQ   2048
#define DIM   1024
#define HEADS 16
#define HD    64
#define MROWS (BATCH*SEQ)   // 4096

// Scratch. Referenced ONLY from device code.
__device__ float g_qp[MROWS*DIM];
__device__ float g_kp[MROWS*DIM];
__device__ float g_vp[MROWS*DIM];
__device__ float g_ao[MROWS*DIM];

// ---------------------------------------------------------------------------
// tf32 helpers (fragment layouts validated in R9/R10)
// ---------------------------------------------------------------------------
__device__ __forceinline__ unsigned f2tf32(float x) {
    unsigned r;
    asm("cvt.rna.tf32.f32 %0, %1;" : "=r"(r) : "f"(x));
    return r;
}
__device__ __forceinline__ uint4 tf32x4(float4 v) {
    return make_uint4(f2tf32(v.x), f2tf32(v.y), f2tf32(v.z), f2tf32(v.w));
}
__device__ __forceinline__ void mma_tf32(float d[4], const unsigned a[4],
                                         const unsigned b[2], const float c[4]) {
    asm volatile(
        "mma.sync.aligned.m16n8k8.row.col.f32.tf32.tf32.f32 "
        "{%0,%1,%2,%3}, {%4,%5,%6,%7}, {%8,%9}, {%10,%11,%12,%13};"
        : "=f"(d[0]), "=f"(d[1]), "=f"(d[2]), "=f"(d[3])
        : "r"(a[0]), "r"(a[1]), "r"(a[2]), "r"(a[3]),
          "r"(b[0]), "r"(b[1]),
          "f"(c[0]), "f"(c[1]), "f"(c[2]), "f"(c[3]));
}

// ---------------------------------------------------------------------------
// tf32 GEMM with register-prefetch double buffering.
// C[M,N] = A[M,K] @ W[K,N] + bias[N]; 128x128 tile, BK=32, 256 thr, 8 warps.
// ---------------------------------------------------------------------------
__device__ __forceinline__ void gemm_tf32_body(const float* __restrict__ A,
                                               const float* __restrict__ W,
                                               const float* __restrict__ bias,
                                               float* __restrict__ C)
{
    __shared__ unsigned As[128][36];
    __shared__ unsigned Bs[32][132];

    const int tid  = threadIdx.x;
    const int lane = tid & 31;
    const int warp = tid >> 5;
    const int wm   = warp >> 2;
    const int wn   = warp & 3;
    const int r    = lane >> 2;
    const int c    = lane & 3;
    const int row0 = blockIdx.y * 128;
    const int col0 = blockIdx.x * 128;

    // Per-thread staging coordinates
    const int ar  = tid >> 3;              // A row within tile (stride 32 over i)... see loop
    const int ac4 = (tid & 7) << 2;
    const int br  = tid >> 5;
    const int bc4 = (tid & 31) << 2;

    float acc[4][4][4];
#pragma unroll
    for (int mt = 0; mt < 4; mt++)
#pragma unroll
        for (int nt = 0; nt < 4; nt++)
#pragma unroll
            for (int e = 0; e < 4; e++) acc[mt][nt][e] = 0.0f;

    float4 pa[4], pb[4];
    // Prefetch k0 = 0
#pragma unroll
    for (int i = 0; i < 4; i++) {
        pa[i] = *(const float4*)(A + (size_t)(row0 + ar + i * 32) * DIM + ac4);
        pb[i] = *(const float4*)(W + (size_t)(br + i * 8) * DIM + col0 + bc4);
    }

    for (int k0 = 0; k0 < DIM; k0 += 32) {
        // Store staged registers to smem (tf32 convert)
#pragma unroll
        for (int i = 0; i < 4; i++) {
            *(uint4*)&As[ar + i * 32][ac4] = tf32x4(pa[i]);
            *(uint4*)&Bs[br + i * 8][bc4]  = tf32x4(pb[i]);
        }
        __syncthreads();

        // Prefetch next tile (overlaps with MMA compute below)
        if (k0 + 32 < DIM) {
#pragma unroll
            for (int i = 0; i < 4; i++) {
                pa[i] = *(const float4*)(A + (size_t)(row0 + ar + i * 32) * DIM + k0 + 32 + ac4);
                pb[i] = *(const float4*)(W + (size_t)(br + i * 8) * DIM + col0 + bc4 + (size_t)(k0 + 32) * DIM);
            }
        }

#pragma unroll
        for (int ks = 0; ks < 4; ks++) {
            const int kk = ks * 8;
            unsigned a[4][4], b[4][2];
#pragma unroll
            for (int mt = 0; mt < 4; mt++) {
                int m = wm * 64 + mt * 16;
                a[mt][0] = As[m + r    ][kk + c    ];
                a[mt][1] = As[m + r + 8][kk + c    ];
                a[mt][2] = As[m + r    ][kk + c + 4];
                a[mt][3] = As[m + r + 8][kk + c + 4];
            }
#pragma unroll
            for (int nt = 0; nt < 4; nt++) {
                int n = wn * 32 + nt * 8 + r;
                b[nt][0] = Bs[kk + c    ][n];
                b[nt][1] = Bs[kk + c + 4][n];
            }
#pragma unroll
            for (int mt = 0; mt < 4; mt++)
#pragma unroll
                for (int nt = 0; nt < 4; nt++)
                    mma_tf32(acc[mt][nt], a[mt], b[nt], acc[mt][nt]);
        }
        __syncthreads();
    }

#pragma unroll
    for (int nt = 0; nt < 4; nt++) {
        int col = col0 + wn * 32 + nt * 8 + 2 * c;
        float b0 = bias[col], b1 = bias[col + 1];
#pragma unroll
        for (int mt = 0; mt < 4; mt++) {
            int row = row0 + wm * 64 + mt * 16 + r;
            float2 lo = make_float2(acc[mt][nt][0] + b0, acc[mt][nt][1] + b1);
            float2 hi = make_float2(acc[mt][nt][2] + b0, acc[mt][nt][3] + b1);
            *(float2*)(C + (size_t)row * DIM + col)       = lo;
            *(float2*)(C + (size_t)(row + 8) * DIM + col) = hi;
        }
    }
}

// Fused QKV projection: grid.z in {0,1,2} selects (Q,Wq,bq)->g_qp etc.
__global__ void __launch_bounds__(256) gemm_qkv_kernel(
    const float* Q, const float* K, const float* V,
    const float* Wq, const float* Wk, const float* Wv,
    const float* bq, const float* bk, const float* bv)
{
    const float *A, *W, *bias;
    float* C;
    if (blockIdx.z == 0)      { A = Q; W = Wq; bias = bq; C = g_qp; }
    else if (blockIdx.z == 1) { A = K; W = Wk; bias = bk; C = g_kp; }
    else                      { A = V; W = Wv; bias = bv; C = g_vp; }
    gemm_tf32_body(A, W, bias, C);
}

__global__ void __launch_bounds__(256) gemm_o_kernel(const float* W, const float* b, float* C)
{
    gemm_tf32_body(g_ao, W, b, C);
}

// ---------------------------------------------------------------------------
// RoPE (corrected direction, validated).
// ---------------------------------------------------------------------------
__global__ void __launch_bounds__(256) rope_kernel()
{
    int idx = blockIdx.x * blockDim.x + threadIdx.x;
    if (idx >= MROWS * (DIM / 2)) return;
    int m = idx >> 9;
    int cc = idx & 511;
    int h = cc >> 5;
    int d = cc & 31;
    int pos = m & (SEQ - 1);

    float invf = 1.0f / powf(10000.0f, (float)d * (1.0f / 32.0f));
    float ang  = (float)pos * invf;
    float cs, sn;
    sincosf(ang, &cs, &sn);

    int base = m * DIM + h * HD + d;
    float q1 = g_qp[base], q2 = g_qp[base + 32];
    g_qp[base]      = q1 * cs + q2 * sn;
    g_qp[base + 32] = q2 * cs - q1 * sn;
    float k1 = g_kp[base], k2 = g_kp[base + 32];
    g_kp[base]      = k1 * cs + k2 * sn;
    g_kp[base + 32] = k2 * cs - k1 * sn;
}

// ---------------------------------------------------------------------------
// tf32 tensor-core causal flash attention (validated in R10).
// ---------------------------------------------------------------------------
#define SM_QS 0
#define SM_KS 4352          // 64*68
#define SM_VS 8704          // + 64*68
#define SM_PS 13312         // + 64*72
#define SM_TOTAL_U32 17664  // + 64*68
#define SM_TOTAL_BYTES (SM_TOTAL_U32*4)

__global__ void __launch_bounds__(128) attn_kernel()
{
    extern __shared__ unsigned sm[];
    unsigned (*Qs)[68] = (unsigned(*)[68])(sm + SM_QS);
    unsigned (*Ks)[68] = (unsigned(*)[68])(sm + SM_KS);
    unsigned (*Vs)[72] = (unsigned(*)[72])(sm + SM_VS);
    unsigned (*Ps)[68] = (unsigned(*)[68])(sm + SM_PS);

    const int tid  = threadIdx.x;
    const int lane = tid & 31;
    const int warp = tid >> 5;
    const int r    = lane >> 2;
    const int c    = lane & 3;
    const int w16  = warp * 16;
    const int qt   = blockIdx.x;
    const int bh   = blockIdx.y;
    const int b    = bh >> 4;
    const int h    = bh & 15;
    const int q0   = qt * 64;
    const size_t headoff = (size_t)h * HD;

#pragma unroll
    for (int i = 0; i < 8; i++) {
        int idx = tid + i * 128;
        int rr  = idx >> 4;
        int c4  = (idx & 15) * 4;
        float4 v = *(const float4*)(g_qp + (size_t)(b * SEQ + q0 + rr) * DIM + headoff + c4);
        v.x *= 0.125f; v.y *= 0.125f; v.z *= 0.125f; v.w *= 0.125f;
        *(uint4*)&Qs[rr][c4] = tf32x4(v);
    }

    float o[8][4];
#pragma unroll
    for (int nt = 0; nt < 8; nt++)
#pragma unroll
        for (int e = 0; e < 4; e++) o[nt][e] = 0.0f;
    float m_a = -1e30f, m_b = -1e30f, l_a = 0.0f, l_b = 0.0f;

    for (int jt = 0; jt <= qt; jt++) {
        const int k0 = jt * 64;
        __syncthreads();
#pragma unroll
        for (int i = 0; i < 8; i++) {
            int idx = tid + i * 128;
            int rr  = idx >> 4;
            int c4  = (idx & 15) * 4;
            size_t g = (size_t)(b * SEQ + k0 + rr) * DIM + headoff + c4;
            *(uint4*)&Ks[rr][c4] = tf32x4(*(const float4*)(g_kp + g));
            *(uint4*)&Vs[rr][c4] = tf32x4(*(const float4*)(g_vp + g));
        }
        __syncthreads();

        float s[8][4];
#pragma unroll
        for (int nt = 0; nt < 8; nt++)
#pragma unroll
            for (int e = 0; e < 4; e++) s[nt][e] = 0.0f;

#pragma unroll
        for (int ks = 0; ks < 8; ks++) {
            const int kk = ks * 8;
            unsigned a[4] = { Qs[w16 + r    ][kk + c    ],
                              Qs[w16 + r + 8][kk + c    ],
                              Qs[w16 + r    ][kk + c + 4],
                              Qs[w16 + r + 8][kk + c + 4] };
#pragma unroll
            for (int nt = 0; nt < 8; nt++) {
                unsigned bf[2] = { Ks[nt * 8 + r][kk + c    ],
                                   Ks[nt * 8 + r][kk + c + 4] };
                mma_tf32(s[nt], a, bf, s[nt]);
            }
        }

        if (jt == qt) {
            const int ra = w16 + r, rb = ra + 8;
#pragma unroll
            for (int nt = 0; nt < 8; nt++) {
                int c0_ = nt * 8 + 2 * c;
                if (c0_     > ra) s[nt][0] = -1e30f;
                if (c0_ + 1 > ra) s[nt][1] = -1e30f;
                if (c0_     > rb) s[nt][2] = -1e30f;
                if (c0_ + 1 > rb) s[nt][3] = -1e30f;
            }
        }

        float mxa = -1e30f, mxb = -1e30f;
#pragma unroll
        for (int nt = 0; nt < 8; nt++) {
            mxa = fmaxf(mxa, fmaxf(s[nt][0], s[nt][1]));
            mxb = fmaxf(mxb, fmaxf(s[nt][2], s[nt][3]));
        }
        mxa = fmaxf(mxa, __shfl_xor_sync(0xffffffffu, mxa, 1));
        mxa = fmaxf(mxa, __shfl_xor_sync(0xffffffffu, mxa, 2));
        mxb = fmaxf(mxb, __shfl_xor_sync(0xffffffffu, mxb, 1));
        mxb = fmaxf(mxb, __shfl_xor_sync(0xffffffffu, mxb, 2));

        float mna = fmaxf(m_a, mxa), mnb = fmaxf(m_b, mxb);
        float corra = __expf(m_a - mna), corrb = __expf(m_b - mnb);
        m_a = mna; m_b = mnb;

        float ra_ = 0.0f, rb_ = 0.0f;
#pragma unroll
        for (int nt = 0; nt < 8; nt++) {
            s[nt][0] = __expf(s[nt][0] - m_a);
            s[nt][1] = __expf(s[nt][1] - m_a);
            s[nt][2] = __expf(s[nt][2] - m_b);
            s[nt][3] = __expf(s[nt][3] - m_b);
            ra_ += s[nt][0] + s[nt][1];
            rb_ += s[nt][2] + s[nt][3];
        }
        ra_ += __shfl_xor_sync(0xffffffffu, ra_, 1);
        ra_ += __shfl_xor_sync(0xffffffffu, ra_, 2);
        rb_ += __shfl_xor_sync(0xffffffffu, rb_, 1);
        rb_ += __shfl_xor_sync(0xffffffffu, rb_, 2);
        l_a = l_a * corra + ra_;
        l_b = l_b * corrb + rb_;

#pragma unroll
        for (int nt = 0; nt < 8; nt++) {
            o[nt][0] *= corra; o[nt][1] *= corra;
            o[nt][2] *= corrb; o[nt][3] *= corrb;
        }

#pragma unroll
        for (int nt = 0; nt < 8; nt++) {
            *(uint2*)&Ps[w16 + r    ][nt * 8 + 2 * c] =
                make_uint2(f2tf32(s[nt][0]), f2tf32(s[nt][1]));
            *(uint2*)&Ps[w16 + r + 8][nt * 8 + 2 * c] =
                make_uint2(f2tf32(s[nt][2]), f2tf32(s[nt][3]));
        }
        __syncwarp();

#pragma unroll
        for (int ks = 0; ks < 8; ks++) {
            const int kk = ks * 8;
            unsigned a[4] = { Ps[w16 + r    ][kk + c    ],
                              Ps[w16 + r + 8][kk + c    ],
                              Ps[w16 + r    ][kk + c + 4],
                              Ps[w16 + r + 8][kk + c + 4] };
#pragma unroll
            for (int nt = 0; nt < 8; nt++) {
                unsigned bf[2] = { Vs[kk + c    ][nt * 8 + r],
                                   Vs[kk + c + 4][nt * 8 + r] };
                mma_tf32(o[nt], a, bf, o[nt]);
            }
        }
    }

    float ia = 1.0f / l_a, ib = 1.0f / l_b;
    size_t rowa = (size_t)(b * SEQ + q0 + w16 + r) * DIM + headoff;
#pragma unroll
    for (int nt = 0; nt < 8; nt++) {
        int col = nt * 8 + 2 * c;
        *(float2*)(g_ao + rowa + col)           = make_float2(o[nt][0] * ia, o[nt][1] * ia);
        *(float2*)(g_ao + rowa + 8 * DIM + col) = make_float2(o[nt][2] * ib, o[nt][3] * ib);
    }
}

// ---------------------------------------------------------------------------
extern "C" void kernel_launch(void* const* d_in, const int* in_sizes, int n_in,
                              void* d_out, int out_size)
{
    const float* Q  = (const float*)d_in[0];
    const float* K  = (const float*)d_in[1];
    const float* V  = (const float*)d_in[2];
    const float* Wq = (const float*)d_in[3];
    const float* Wk = (const float*)d_in[4];
    const float* Wv = (const float*)d_in[5];
    const float* Wo = (const float*)d_in[6];
    const float* bq = (const float*)d_in[7];
    const float* bk = (const float*)d_in[8];
    const float* bv = (const float*)d_in[9];
    const float* bo = (const float*)d_in[10];
    float* out = (float*)d_out;

    cudaFuncSetAttribute(attn_kernel, cudaFuncAttributeMaxDynamicSharedMemorySize,
                         SM_TOTAL_BYTES);

    dim3 gqkv(DIM / 128, MROWS / 128, 3);   // (8, 32, 3) = 768 CTAs
    gemm_qkv_kernel<<<gqkv, 256>>>(Q, K, V, Wq, Wk, Wv, bq, bk, bv);
    rope_kernel<<<(MROWS * (DIM / 2)) / 256, 256>>>();
    attn_kernel<<<dim3(SEQ / 64, BATCH * HEADS), 128, SM_TOTAL_BYTES>>>();
    gemm_o_kernel<<<dim3(DIM / 128, MROWS / 128), 256>>>(Wo, bo, out);
}

// round 12
// speedup vs baseline: 15.4832x; 1.0230x over previous
#include <cuda_runtime.h>
#include <math.h>

#define BATCH 2
#define SEQ   2048
#define DIM   1024
#define HEADS 16
#define HD    64
#define MROWS (BATCH*SEQ)   // 4096

// Scratch. Referenced ONLY from device code.
// After rope_kernel, g_qp/g_kp/g_vp hold tf32 BIT PATTERNS (q pre-scaled 1/8).
__device__ float g_qp[MROWS*DIM];
__device__ float g_kp[MROWS*DIM];
__device__ float g_vp[MROWS*DIM];
__device__ float g_ao[MROWS*DIM];

// ---------------------------------------------------------------------------
// tf32 helpers (fragment layouts validated R9-R11)
// ---------------------------------------------------------------------------
__device__ __forceinline__ unsigned f2tf32(float x) {
    unsigned r;
    asm("cvt.rna.tf32.f32 %0, %1;" : "=r"(r) : "f"(x));
    return r;
}
__device__ __forceinline__ uint4 tf32x4(float4 v) {
    return make_uint4(f2tf32(v.x), f2tf32(v.y), f2tf32(v.z), f2tf32(v.w));
}
__device__ __forceinline__ void mma_tf32(float d[4], const unsigned a[4],
                                         const unsigned b[2], const float c[4]) {
    asm volatile(
        "mma.sync.aligned.m16n8k8.row.col.f32.tf32.tf32.f32 "
        "{%0,%1,%2,%3}, {%4,%5,%6,%7}, {%8,%9}, {%10,%11,%12,%13};"
        : "=f"(d[0]), "=f"(d[1]), "=f"(d[2]), "=f"(d[3])
        : "r"(a[0]), "r"(a[1]), "r"(a[2]), "r"(a[3]),
          "r"(b[0]), "r"(b[1]),
          "f"(c[0]), "f"(c[1]), "f"(c[2]), "f"(c[3]));
}

// ---------------------------------------------------------------------------
// tf32 GEMM, register prefetch + SMEM DOUBLE BUFFER (1 sync/iter).
// Pads: A 36 (bank 4r+c unique), B 136 (bank 8c+r unique — conflict fix).
// Dynamic smem: As0[128*36], As1, Bs0[32*136], Bs1 = 71680 B.
// ---------------------------------------------------------------------------
#define GS_AS0 0
#define GS_AS1 4608
#define GS_BS0 9216
#define GS_BS1 13568
#define GS_TOTAL_U32 17920
#define GS_BYTES (GS_TOTAL_U32*4)

__device__ __forceinline__ void gemm_tf32_body(const float* __restrict__ A,
                                               const float* __restrict__ W,
                                               const float* __restrict__ bias,
                                               float* __restrict__ C)
{
    extern __shared__ unsigned gsm[];

    const int tid  = threadIdx.x;
    const int lane = tid & 31;
    const int warp = tid >> 5;
    const int wm   = warp >> 2;
    const int wn   = warp & 3;
    const int r    = lane >> 2;
    const int c    = lane & 3;
    const int row0 = blockIdx.y * 128;
    const int col0 = blockIdx.x * 128;

    const int ar  = tid >> 3;
    const int ac4 = (tid & 7) << 2;
    const int br  = tid >> 5;
    const int bc4 = (tid & 31) << 2;

    float acc[4][4][4];
#pragma unroll
    for (int mt = 0; mt < 4; mt++)
#pragma unroll
        for (int nt = 0; nt < 4; nt++)
#pragma unroll
            for (int e = 0; e < 4; e++) acc[mt][nt][e] = 0.0f;

    float4 pa[4], pb[4];
#pragma unroll
    for (int i = 0; i < 4; i++) {
        pa[i] = *(const float4*)(A + (size_t)(row0 + ar + i * 32) * DIM + ac4);
        pb[i] = *(const float4*)(W + (size_t)(br + i * 8) * DIM + col0 + bc4);
    }
    {
        unsigned* As = gsm + GS_AS0;
        unsigned* Bs = gsm + GS_BS0;
#pragma unroll
        for (int i = 0; i < 4; i++) {
            *(uint4*)(As + (ar + i * 32) * 36 + ac4) = tf32x4(pa[i]);
            *(uint4*)(Bs + (br + i * 8) * 136 + bc4) = tf32x4(pb[i]);
        }
    }
    __syncthreads();

    for (int k0 = 0; k0 < DIM; k0 += 32) {
        const int cur = (k0 >> 5) & 1;
        unsigned* As = gsm + (cur ? GS_AS1 : GS_AS0);
        unsigned* Bs = gsm + (cur ? GS_BS1 : GS_BS0);
        const bool more = (k0 + 32 < DIM);

        // Prefetch next tile into registers (overlaps the MMAs below)
        if (more) {
#pragma unroll
            for (int i = 0; i < 4; i++) {
                pa[i] = *(const float4*)(A + (size_t)(row0 + ar + i * 32) * DIM + k0 + 32 + ac4);
                pb[i] = *(const float4*)(W + (size_t)(k0 + 32 + br + i * 8) * DIM + col0 + bc4);
            }
        }

#pragma unroll
        for (int ks = 0; ks < 4; ks++) {
            const int kk = ks * 8;
            unsigned a[4][4], b[4][2];
#pragma unroll
            for (int mt = 0; mt < 4; mt++) {
                int m = wm * 64 + mt * 16;
                a[mt][0] = As[(m + r    ) * 36 + kk + c    ];
                a[mt][1] = As[(m + r + 8) * 36 + kk + c    ];
                a[mt][2] = As[(m + r    ) * 36 + kk + c + 4];
                a[mt][3] = As[(m + r + 8) * 36 + kk + c + 4];
            }
#pragma unroll
            for (int nt = 0; nt < 4; nt++) {
                int n = wn * 32 + nt * 8 + r;
                b[nt][0] = Bs[(kk + c    ) * 136 + n];
                b[nt][1] = Bs[(kk + c + 4) * 136 + n];
            }
#pragma unroll
            for (int mt = 0; mt < 4; mt++)
#pragma unroll
                for (int nt = 0; nt < 4; nt++)
                    mma_tf32(acc[mt][nt], a[mt], b[nt], acc[mt][nt]);
        }

        // Store prefetched tile into the OTHER buffer; no second sync needed.
        if (more) {
            unsigned* Asn = gsm + (cur ? GS_AS0 : GS_AS1);
            unsigned* Bsn = gsm + (cur ? GS_BS0 : GS_BS1);
#pragma unroll
            for (int i = 0; i < 4; i++) {
                *(uint4*)(Asn + (ar + i * 32) * 36 + ac4) = tf32x4(pa[i]);
                *(uint4*)(Bsn + (br + i * 8) * 136 + bc4) = tf32x4(pb[i]);
            }
        }
        __syncthreads();
    }

#pragma unroll
    for (int nt = 0; nt < 4; nt++) {
        int col = col0 + wn * 32 + nt * 8 + 2 * c;
        float b0 = bias[col], b1 = bias[col + 1];
#pragma unroll
        for (int mt = 0; mt < 4; mt++) {
            int row = row0 + wm * 64 + mt * 16 + r;
            float2 lo = make_float2(acc[mt][nt][0] + b0, acc[mt][nt][1] + b1);
            float2 hi = make_float2(acc[mt][nt][2] + b0, acc[mt][nt][3] + b1);
            *(float2*)(C + (size_t)row * DIM + col)       = lo;
            *(float2*)(C + (size_t)(row + 8) * DIM + col) = hi;
        }
    }
}

__global__ void __launch_bounds__(256, 2) gemm_qkv_kernel(
    const float* Q, const float* K, const float* V,
    const float* Wq, const float* Wk, const float* Wv,
    const float* bq, const float* bk, const float* bv)
{
    const float *A, *W, *bias;
    float* C;
    if (blockIdx.z == 0)      { A = Q; W = Wq; bias = bq; C = g_qp; }
    else if (blockIdx.z == 1) { A = K; W = Wk; bias = bk; C = g_kp; }
    else                      { A = V; W = Wv; bias = bv; C = g_vp; }
    gemm_tf32_body(A, W, bias, C);
}

__global__ void __launch_bounds__(256, 2) gemm_o_kernel(const float* W, const float* b, float* C)
{
    gemm_tf32_body(g_ao, W, b, C);
}

// ---------------------------------------------------------------------------
// RoPE + tf32 pre-conversion (in place):
//   q <- tf32(rope(q) * 0.125), k <- tf32(rope(k)), v <- tf32(v)
// Rotation (validated): out1 = x1*cos + x2*sin; out2 = x2*cos - x1*sin.
// Downstream attention reads these arrays as tf32 bit patterns.
// ---------------------------------------------------------------------------
__global__ void __launch_bounds__(256) rope_kernel()
{
    int idx = blockIdx.x * blockDim.x + threadIdx.x;
    if (idx >= MROWS * (DIM / 2)) return;
    int m = idx >> 9;
    int cc = idx & 511;
    int h = cc >> 5;
    int d = cc & 31;
    int pos = m & (SEQ - 1);

    float invf = 1.0f / powf(10000.0f, (float)d * (1.0f / 32.0f));
    float ang  = (float)pos * invf;
    float cs, sn;
    sincosf(ang, &cs, &sn);

    int base = m * DIM + h * HD + d;
    unsigned* qo = (unsigned*)g_qp;
    unsigned* ko = (unsigned*)g_kp;
    unsigned* vo = (unsigned*)g_vp;

    float q1 = g_qp[base], q2 = g_qp[base + 32];
    qo[base]      = f2tf32((q1 * cs + q2 * sn) * 0.125f);
    qo[base + 32] = f2tf32((q2 * cs - q1 * sn) * 0.125f);
    float k1 = g_kp[base], k2 = g_kp[base + 32];
    ko[base]      = f2tf32(k1 * cs + k2 * sn);
    ko[base + 32] = f2tf32(k2 * cs - k1 * sn);
    float v1 = g_vp[base], v2 = g_vp[base + 32];
    vo[base]      = f2tf32(v1);
    vo[base + 32] = f2tf32(v2);
}

// ---------------------------------------------------------------------------
// tf32 tensor-core causal flash attention. Staging is now PURE COPY
// (operands pre-converted by rope_kernel).
// ---------------------------------------------------------------------------
#define SM_QS 0
#define SM_KS 4352          // 64*68
#define SM_VS 8704          // + 64*68
#define SM_PS 13312         // + 64*72
#define SM_TOTAL_U32 17664  // + 64*68
#define SM_TOTAL_BYTES (SM_TOTAL_U32*4)

__global__ void __launch_bounds__(128) attn_kernel()
{
    extern __shared__ unsigned sm[];
    unsigned (*Qs)[68] = (unsigned(*)[68])(sm + SM_QS);
    unsigned (*Ks)[68] = (unsigned(*)[68])(sm + SM_KS);
    unsigned (*Vs)[72] = (unsigned(*)[72])(sm + SM_VS);
    unsigned (*Ps)[68] = (unsigned(*)[68])(sm + SM_PS);

    const int tid  = threadIdx.x;
    const int lane = tid & 31;
    const int warp = tid >> 5;
    const int r    = lane >> 2;
    const int c    = lane & 3;
    const int w16  = warp * 16;
    const int qt   = blockIdx.x;
    const int bh   = blockIdx.y;
    const int b    = bh >> 4;
    const int h    = bh & 15;
    const int q0   = qt * 64;
    const size_t headoff = (size_t)h * HD;

    const unsigned* qsrc = (const unsigned*)g_qp;
    const unsigned* ksrc = (const unsigned*)g_kp;
    const unsigned* vsrc = (const unsigned*)g_vp;

#pragma unroll
    for (int i = 0; i < 8; i++) {
        int idx = tid + i * 128;
        int rr  = idx >> 4;
        int c4  = (idx & 15) * 4;
        *(uint4*)&Qs[rr][c4] =
            *(const uint4*)(qsrc + (size_t)(b * SEQ + q0 + rr) * DIM + headoff + c4);
    }

    float o[8][4];
#pragma unroll
    for (int nt = 0; nt < 8; nt++)
#pragma unroll
        for (int e = 0; e < 4; e++) o[nt][e] = 0.0f;
    float m_a = -1e30f, m_b = -1e30f, l_a = 0.0f, l_b = 0.0f;

    for (int jt = 0; jt <= qt; jt++) {
        const int k0 = jt * 64;
        __syncthreads();
#pragma unroll
        for (int i = 0; i < 8; i++) {
            int idx = tid + i * 128;
            int rr  = idx >> 4;
            int c4  = (idx & 15) * 4;
            size_t g = (size_t)(b * SEQ + k0 + rr) * DIM + headoff + c4;
            *(uint4*)&Ks[rr][c4] = *(const uint4*)(ksrc + g);
            *(uint4*)&Vs[rr][c4] = *(const uint4*)(vsrc + g);
        }
        __syncthreads();

        float s[8][4];
#pragma unroll
        for (int nt = 0; nt < 8; nt++)
#pragma unroll
            for (int e = 0; e < 4; e++) s[nt][e] = 0.0f;

#pragma unroll
        for (int ks = 0; ks < 8; ks++) {
            const int kk = ks * 8;
            unsigned a[4] = { Qs[w16 + r    ][kk + c    ],
                              Qs[w16 + r + 8][kk + c    ],
                              Qs[w16 + r    ][kk + c + 4],
                              Qs[w16 + r + 8][kk + c + 4] };
#pragma unroll
            for (int nt = 0; nt < 8; nt++) {
                unsigned bf[2] = { Ks[nt * 8 + r][kk + c    ],
                                   Ks[nt * 8 + r][kk + c + 4] };
                mma_tf32(s[nt], a, bf, s[nt]);
            }
        }

        if (jt == qt) {
            const int ra = w16 + r, rb = ra + 8;
#pragma unroll
            for (int nt = 0; nt < 8; nt++) {
                int c0_ = nt * 8 + 2 * c;
                if (c0_     > ra) s[nt][0] = -1e30f;
                if (c0_ + 1 > ra) s[nt][1] = -1e30f;
                if (c0_     > rb) s[nt][2] = -1e30f;
                if (c0_ + 1 > rb) s[nt][3] = -1e30f;
            }
        }

        float mxa = -1e30f, mxb = -1e30f;
#pragma unroll
        for (int nt = 0; nt < 8; nt++) {
            mxa = fmaxf(mxa, fmaxf(s[nt][0], s[nt][1]));
            mxb = fmaxf(mxb, fmaxf(s[nt][2], s[nt][3]));
        }
        mxa = fmaxf(mxa, __shfl_xor_sync(0xffffffffu, mxa, 1));
        mxa = fmaxf(mxa, __shfl_xor_sync(0xffffffffu, mxa, 2));
        mxb = fmaxf(mxb, __shfl_xor_sync(0xffffffffu, mxb, 1));
        mxb = fmaxf(mxb, __shfl_xor_sync(0xffffffffu, mxb, 2));

        float mna = fmaxf(m_a, mxa), mnb = fmaxf(m_b, mxb);
        float corra = __expf(m_a - mna), corrb = __expf(m_b - mnb);
        m_a = mna; m_b = mnb;

        float ra_ = 0.0f, rb_ = 0.0f;
#pragma unroll
        for (int nt = 0; nt < 8; nt++) {
            s[nt][0] = __expf(s[nt][0] - m_a);
            s[nt][1] = __expf(s[nt][1] - m_a);
            s[nt][2] = __expf(s[nt][2] - m_b);
            s[nt][3] = __expf(s[nt][3] - m_b);
            ra_ += s[nt][0] + s[nt][1];
            rb_ += s[nt][2] + s[nt][3];
        }
        ra_ += __shfl_xor_sync(0xffffffffu, ra_, 1);
        ra_ += __shfl_xor_sync(0xffffffffu, ra_, 2);
        rb_ += __shfl_xor_sync(0xffffffffu, rb_, 1);
        rb_ += __shfl_xor_sync(0xffffffffu, rb_, 2);
        l_a = l_a * corra + ra_;
        l_b = l_b * corrb + rb_;

#pragma unroll
        for (int nt = 0; nt < 8; nt++) {
            o[nt][0] *= corra; o[nt][1] *= corra;
            o[nt][2] *= corrb; o[nt][3] *= corrb;
        }

#pragma unroll
        for (int nt = 0; nt < 8; nt++) {
            *(uint2*)&Ps[w16 + r    ][nt * 8 + 2 * c] =
                make_uint2(f2tf32(s[nt][0]), f2tf32(s[nt][1]));
            *(uint2*)&Ps[w16 + r + 8][nt * 8 + 2 * c] =
                make_uint2(f2tf32(s[nt][2]), f2tf32(s[nt][3]));
        }
        __syncwarp();

#pragma unroll
        for (int ks = 0; ks < 8; ks++) {
            const int kk = ks * 8;
            unsigned a[4] = { Ps[w16 + r    ][kk + c    ],
                              Ps[w16 + r + 8][kk + c    ],
                              Ps[w16 + r    ][kk + c + 4],
                              Ps[w16 + r + 8][kk + c + 4] };
#pragma unroll
            for (int nt = 0; nt < 8; nt++) {
                unsigned bf[2] = { Vs[kk + c    ][nt * 8 + r],
                                   Vs[kk + c + 4][nt * 8 + r] };
                mma_tf32(o[nt], a, bf, o[nt]);
            }
        }
    }

    float ia = 1.0f / l_a, ib = 1.0f / l_b;
    size_t rowa = (size_t)(b * SEQ + q0 + w16 + r) * DIM + headoff;
#pragma unroll
    for (int nt = 0; nt < 8; nt++) {
        int col = nt * 8 + 2 * c;
        *(float2*)(g_ao + rowa + col)           = make_float2(o[nt][0] * ia, o[nt][1] * ia);
        *(float2*)(g_ao + rowa + 8 * DIM + col) = make_float2(o[nt][2] * ib, o[nt][3] * ib);
    }
}

// ---------------------------------------------------------------------------
extern "C" void kernel_launch(void* const* d_in, const int* in_sizes, int n_in,
                              void* d_out, int out_size)
{
    const float* Q  = (const float*)d_in[0];
    const float* K  = (const float*)d_in[1];
    const float* V  = (const float*)d_in[2];
    const float* Wq = (const float*)d_in[3];
    const float* Wk = (const float*)d_in[4];
    const float* Wv = (const float*)d_in[5];
    const float* Wo = (const float*)d_in[6];
    const float* bq = (const float*)d_in[7];
    const float* bk = (const float*)d_in[8];
    const float* bv = (const float*)d_in[9];
    const float* bo = (const float*)d_in[10];
    float* out = (float*)d_out;

    cudaFuncSetAttribute(attn_kernel, cudaFuncAttributeMaxDynamicSharedMemorySize,
                         SM_TOTAL_BYTES);
    cudaFuncSetAttribute(gemm_qkv_kernel, cudaFuncAttributeMaxDynamicSharedMemorySize,
                         GS_BYTES);
    cudaFuncSetAttribute(gemm_o_kernel, cudaFuncAttributeMaxDynamicSharedMemorySize,
                         GS_BYTES);

    dim3 gqkv(DIM / 128, MROWS / 128, 3);   // 768 CTAs
    gemm_qkv_kernel<<<gqkv, 256, GS_BYTES>>>(Q, K, V, Wq, Wk, Wv, bq, bk, bv);
    rope_kernel<<<(MROWS * (DIM / 2)) / 256, 256>>>();
    attn_kernel<<<dim3(SEQ / 64, BATCH * HEADS), 128, SM_TOTAL_BYTES>>>();
    gemm_o_kernel<<<dim3(DIM / 128, MROWS / 128), 256, GS_BYTES>>>(Wo, bo, out);
}

// round 13
// speedup vs baseline: 16.2788x; 1.0514x over previous
#include <cuda_runtime.h>
#include <math.h>

#define BATCH 2
#define SEQ   2048
#define DIM   1024
#define HEADS 16
#define HD    64
#define MROWS (BATCH*SEQ)   // 4096

// Scratch. Referenced ONLY from device code.
__device__ float    g_qp[MROWS*DIM];    // fp32 QKV projections (rope input)
__device__ float    g_kp[MROWS*DIM];
__device__ float    g_vp[MROWS*DIM];
__device__ unsigned g_ao[MROWS*DIM];    // attention out, tf32 bits (RNA)
// Pre-converted tf32 bit patterns (RNA) of GEMM operands:
__device__ unsigned g_q32[MROWS*DIM];
__device__ unsigned g_k32[MROWS*DIM];
__device__ unsigned g_v32[MROWS*DIM];
__device__ unsigned g_w32[4][DIM*DIM];  // Wq, Wk, Wv, Wo

// ---------------------------------------------------------------------------
// tf32 helpers (fragment layouts validated R9-R12)
// ---------------------------------------------------------------------------
__device__ __forceinline__ unsigned f2tf32(float x) {
    unsigned r;
    asm("cvt.rna.tf32.f32 %0, %1;" : "=r"(r) : "f"(x));
    return r;
}
__device__ __forceinline__ uint4 tf32x4(float4 v) {
    return make_uint4(f2tf32(v.x), f2tf32(v.y), f2tf32(v.z), f2tf32(v.w));
}
__device__ __forceinline__ void mma_tf32(float d[4], const unsigned a[4],
                                         const unsigned b[2], const float c[4]) {
    asm volatile(
        "mma.sync.aligned.m16n8k8.row.col.f32.tf32.tf32.f32 "
        "{%0,%1,%2,%3}, {%4,%5,%6,%7}, {%8,%9}, {%10,%11,%12,%13};"
        : "=f"(d[0]), "=f"(d[1]), "=f"(d[2]), "=f"(d[3])
        : "r"(a[0]), "r"(a[1]), "r"(a[2]), "r"(a[3]),
          "r"(b[0]), "r"(b[1]),
          "f"(c[0]), "f"(c[1]), "f"(c[2]), "f"(c[3]));
}
__device__ __forceinline__ void cp16(unsigned* smem_dst, const unsigned* gsrc) {
    unsigned daddr = (unsigned)__cvta_generic_to_shared(smem_dst);
    asm volatile("cp.async.cg.shared.global [%0], [%1], 16;"
                 :: "r"(daddr), "l"(gsrc) : "memory");
}
__device__ __forceinline__ void cp_commit() {
    asm volatile("cp.async.commit_group;" ::: "memory");
}
__device__ __forceinline__ void cp_wait0() {
    asm volatile("cp.async.wait_group 0;" ::: "memory");
}

// ---------------------------------------------------------------------------
// Pre-convert fp32 -> tf32(RNA) bit patterns for all GEMM operands.
// grid (4096,1,7); z: 0..2 -> Q/K/V (4.19M), 3..6 -> Wq/Wk/Wv/Wo (1.05M).
// ---------------------------------------------------------------------------
__global__ void __launch_bounds__(256) preconvert_kernel(
    const float* Q, const float* K, const float* V,
    const float* Wq, const float* Wk, const float* Wv, const float* Wo)
{
    const int z = blockIdx.z;
    const float* src; unsigned* dst; int nblk;
    switch (z) {
        case 0: src = Q;  dst = g_q32;    nblk = 4096; break;
        case 1: src = K;  dst = g_k32;    nblk = 4096; break;
        case 2: src = V;  dst = g_v32;    nblk = 4096; break;
        case 3: src = Wq; dst = g_w32[0]; nblk = 1024; break;
        case 4: src = Wk; dst = g_w32[1]; nblk = 1024; break;
        case 5: src = Wv; dst = g_w32[2]; nblk = 1024; break;
        default:src = Wo; dst = g_w32[3]; nblk = 1024; break;
    }
    if (blockIdx.x >= (unsigned)nblk) return;
    size_t i4 = ((size_t)blockIdx.x * 256 + threadIdx.x) * 4;
    float4 v = *(const float4*)(src + i4);
    *(uint4*)(dst + i4) = tf32x4(v);
}

// ---------------------------------------------------------------------------
// tf32 GEMM: pre-converted operands, cp.async staging, smem double buffer.
// Block 128x128, BK=32, 128 threads = 4 warps (2x2), warp tile 64x64.
// Pads: A 36 (frag bank 4r+c), B 136 (frag bank 8c+r) — both conflict-free.
// ---------------------------------------------------------------------------
#define GS_AS0 0
#define GS_AS1 4608
#define GS_BS0 9216
#define GS_BS1 13568
#define GS_TOTAL_U32 17920
#define GS_BYTES (GS_TOTAL_U32*4)

__device__ __forceinline__ void gemm_stage(unsigned* As, unsigned* Bs,
                                           const unsigned* __restrict__ A32,
                                           const unsigned* __restrict__ W32,
                                           int row0, int col0, int k0, int tid)
{
#pragma unroll
    for (int i = 0; i < 8; i++) {          // A: 128 rows x 32 k = 1024 chunks
        int ch = tid + i * 128;
        int rr = ch >> 3;
        int cw = (ch & 7) << 2;
        cp16(As + rr * 36 + cw, A32 + (size_t)(row0 + rr) * DIM + k0 + cw);
    }
#pragma unroll
    for (int i = 0; i < 8; i++) {          // B: 32 k x 128 n = 1024 chunks
        int ch = tid + i * 128;
        int rr = ch >> 5;
        int cw = (ch & 31) << 2;
        cp16(Bs + rr * 136 + cw, W32 + (size_t)(k0 + rr) * DIM + col0 + cw);
    }
    cp_commit();
}

__device__ __forceinline__ void gemm_tf32_body(const unsigned* __restrict__ A32,
                                               const unsigned* __restrict__ W32,
                                               const float* __restrict__ bias,
                                               float* __restrict__ C)
{
    extern __shared__ unsigned gsm[];

    const int tid  = threadIdx.x;
    const int lane = tid & 31;
    const int warp = tid >> 5;       // 0..3
    const int wm   = warp >> 1;      // 0..1
    const int wn   = warp & 1;       // 0..1
    const int r    = lane >> 2;
    const int c    = lane & 3;
    const int row0 = blockIdx.y * 128;
    const int col0 = blockIdx.x * 128;

    float acc[4][8][4];
#pragma unroll
    for (int mt = 0; mt < 4; mt++)
#pragma unroll
        for (int nt = 0; nt < 8; nt++)
#pragma unroll
            for (int e = 0; e < 4; e++) acc[mt][nt][e] = 0.0f;

    gemm_stage(gsm + GS_AS0, gsm + GS_BS0, A32, W32, row0, col0, 0, tid);
    cp_wait0();
    __syncthreads();

    for (int k0 = 0; k0 < DIM; k0 += 32) {
        const int cur = (k0 >> 5) & 1;
        unsigned* As = gsm + (cur ? GS_AS1 : GS_AS0);
        unsigned* Bs = gsm + (cur ? GS_BS1 : GS_BS0);
        const bool more = (k0 + 32 < DIM);

        if (more)
            gemm_stage(gsm + (cur ? GS_AS0 : GS_AS1), gsm + (cur ? GS_BS0 : GS_BS1),
                       A32, W32, row0, col0, k0 + 32, tid);

#pragma unroll
        for (int ks = 0; ks < 4; ks++) {
            const int kk = ks * 8;
            unsigned a[4][4], b[8][2];
#pragma unroll
            for (int mt = 0; mt < 4; mt++) {
                int m = wm * 64 + mt * 16;
                a[mt][0] = As[(m + r    ) * 36 + kk + c    ];
                a[mt][1] = As[(m + r + 8) * 36 + kk + c    ];
                a[mt][2] = As[(m + r    ) * 36 + kk + c + 4];
                a[mt][3] = As[(m + r + 8) * 36 + kk + c + 4];
            }
#pragma unroll
            for (int nt = 0; nt < 8; nt++) {
                int n = wn * 64 + nt * 8 + r;
                b[nt][0] = Bs[(kk + c    ) * 136 + n];
                b[nt][1] = Bs[(kk + c + 4) * 136 + n];
            }
#pragma unroll
            for (int mt = 0; mt < 4; mt++)
#pragma unroll
                for (int nt = 0; nt < 8; nt++)
                    mma_tf32(acc[mt][nt], a[mt], b[nt], acc[mt][nt]);
        }

        if (more) cp_wait0();
        __syncthreads();
    }

#pragma unroll
    for (int nt = 0; nt < 8; nt++) {
        int col = col0 + wn * 64 + nt * 8 + 2 * c;
        float b0 = bias[col], b1 = bias[col + 1];
#pragma unroll
        for (int mt = 0; mt < 4; mt++) {
            int row = row0 + wm * 64 + mt * 16 + r;
            float2 lo = make_float2(acc[mt][nt][0] + b0, acc[mt][nt][1] + b1);
            float2 hi = make_float2(acc[mt][nt][2] + b0, acc[mt][nt][3] + b1);
            *(float2*)(C + (size_t)row * DIM + col)       = lo;
            *(float2*)(C + (size_t)(row + 8) * DIM + col) = hi;
        }
    }
}

__global__ void __launch_bounds__(128) gemm_qkv_kernel(
    const float* bq, const float* bk, const float* bv)
{
    if (blockIdx.z == 0)      gemm_tf32_body(g_q32, g_w32[0], bq, g_qp);
    else if (blockIdx.z == 1) gemm_tf32_body(g_k32, g_w32[1], bk, g_kp);
    else                      gemm_tf32_body(g_v32, g_w32[2], bv, g_vp);
}

__global__ void __launch_bounds__(128) gemm_o_kernel(const float* bo, float* C)
{
    gemm_tf32_body(g_ao, g_w32[3], bo, C);
}

// ---------------------------------------------------------------------------
// RoPE + tf32 pre-conversion in place (validated R12):
//   q <- tf32(rope(q)*0.125), k <- tf32(rope(k)), v <- tf32(v)
// ---------------------------------------------------------------------------
__global__ void __launch_bounds__(256) rope_kernel()
{
    int idx = blockIdx.x * blockDim.x + threadIdx.x;
    if (idx >= MROWS * (DIM / 2)) return;
    int m = idx >> 9;
    int cc = idx & 511;
    int h = cc >> 5;
    int d = cc & 31;
    int pos = m & (SEQ - 1);

    float invf = 1.0f / powf(10000.0f, (float)d * (1.0f / 32.0f));
    float ang  = (float)pos * invf;
    float cs, sn;
    sincosf(ang, &cs, &sn);

    int base = m * DIM + h * HD + d;
    unsigned* qo = (unsigned*)g_qp;
    unsigned* ko = (unsigned*)g_kp;
    unsigned* vo = (unsigned*)g_vp;

    float q1 = g_qp[base], q2 = g_qp[base + 32];
    qo[base]      = f2tf32((q1 * cs + q2 * sn) * 0.125f);
    qo[base + 32] = f2tf32((q2 * cs - q1 * sn) * 0.125f);
    float k1 = g_kp[base], k2 = g_kp[base + 32];
    ko[base]      = f2tf32(k1 * cs + k2 * sn);
    ko[base + 32] = f2tf32(k2 * cs - k1 * sn);
    float v1 = g_vp[base], v2 = g_vp[base + 32];
    vo[base]      = f2tf32(v1);
    vo[base + 32] = f2tf32(v2);
}

// ---------------------------------------------------------------------------
// tf32 tensor-core causal flash attention with BALANCED PAIRING:
// CTA x processes query tiles {x, 31-x} -> exactly 33 k-tiles per CTA.
// Grid (16, 32); 128 threads, 4 warps. Output written as tf32 bits (RNA).
// ---------------------------------------------------------------------------
#define SM_QS 0
#define SM_KS 4352
#define SM_VS 8704
#define SM_PS 13312
#define SM_TOTAL_U32 17664
#define SM_TOTAL_BYTES (SM_TOTAL_U32*4)

__device__ __forceinline__ void attn_one(int qt, int b, int h,
                                         unsigned (*Qs)[68], unsigned (*Ks)[68],
                                         unsigned (*Vs)[72], unsigned (*Ps)[68])
{
    const int tid  = threadIdx.x;
    const int lane = tid & 31;
    const int warp = tid >> 5;
    const int r    = lane >> 2;
    const int c    = lane & 3;
    const int w16  = warp * 16;
    const int q0   = qt * 64;
    const size_t headoff = (size_t)h * HD;

    const unsigned* qsrc = (const unsigned*)g_qp;
    const unsigned* ksrc = (const unsigned*)g_kp;
    const unsigned* vsrc = (const unsigned*)g_vp;

#pragma unroll
    for (int i = 0; i < 8; i++) {
        int idx = tid + i * 128;
        int rr  = idx >> 4;
        int c4  = (idx & 15) * 4;
        *(uint4*)&Qs[rr][c4] =
            *(const uint4*)(qsrc + (size_t)(b * SEQ + q0 + rr) * DIM + headoff + c4);
    }

    float o[8][4];
#pragma unroll
    for (int nt = 0; nt < 8; nt++)
#pragma unroll
        for (int e = 0; e < 4; e++) o[nt][e] = 0.0f;
    float m_a = -1e30f, m_b = -1e30f, l_a = 0.0f, l_b = 0.0f;

    for (int jt = 0; jt <= qt; jt++) {
        const int k0 = jt * 64;
        __syncthreads();
#pragma unroll
        for (int i = 0; i < 8; i++) {
            int idx = tid + i * 128;
            int rr  = idx >> 4;
            int c4  = (idx & 15) * 4;
            size_t g = (size_t)(b * SEQ + k0 + rr) * DIM + headoff + c4;
            *(uint4*)&Ks[rr][c4] = *(const uint4*)(ksrc + g);
            *(uint4*)&Vs[rr][c4] = *(const uint4*)(vsrc + g);
        }
        __syncthreads();

        float s[8][4];
#pragma unroll
        for (int nt = 0; nt < 8; nt++)
#pragma unroll
            for (int e = 0; e < 4; e++) s[nt][e] = 0.0f;

#pragma unroll
        for (int ks = 0; ks < 8; ks++) {
            const int kk = ks * 8;
            unsigned a[4] = { Qs[w16 + r    ][kk + c    ],
                              Qs[w16 + r + 8][kk + c    ],
                              Qs[w16 + r    ][kk + c + 4],
                              Qs[w16 + r + 8][kk + c + 4] };
#pragma unroll
            for (int nt = 0; nt < 8; nt++) {
                unsigned bf[2] = { Ks[nt * 8 + r][kk + c    ],
                                   Ks[nt * 8 + r][kk + c + 4] };
                mma_tf32(s[nt], a, bf, s[nt]);
            }
        }

        if (jt == qt) {
            const int ra = w16 + r, rb = ra + 8;
#pragma unroll
            for (int nt = 0; nt < 8; nt++) {
                int c0_ = nt * 8 + 2 * c;
                if (c0_     > ra) s[nt][0] = -1e30f;
                if (c0_ + 1 > ra) s[nt][1] = -1e30f;
                if (c0_     > rb) s[nt][2] = -1e30f;
                if (c0_ + 1 > rb) s[nt][3] = -1e30f;
            }
        }

        float mxa = -1e30f, mxb = -1e30f;
#pragma unroll
        for (int nt = 0; nt < 8; nt++) {
            mxa = fmaxf(mxa, fmaxf(s[nt][0], s[nt][1]));
            mxb = fmaxf(mxb, fmaxf(s[nt][2], s[nt][3]));
        }
        mxa = fmaxf(mxa, __shfl_xor_sync(0xffffffffu, mxa, 1));
        mxa = fmaxf(mxa, __shfl_xor_sync(0xffffffffu, mxa, 2));
        mxb = fmaxf(mxb, __shfl_xor_sync(0xffffffffu, mxb, 1));
        mxb = fmaxf(mxb, __shfl_xor_sync(0xffffffffu, mxb, 2));

        float mna = fmaxf(m_a, mxa), mnb = fmaxf(m_b, mxb);
        float corra = __expf(m_a - mna), corrb = __expf(m_b - mnb);
        m_a = mna; m_b = mnb;

        float ra_ = 0.0f, rb_ = 0.0f;
#pragma unroll
        for (int nt = 0; nt < 8; nt++) {
            s[nt][0] = __expf(s[nt][0] - m_a);
            s[nt][1] = __expf(s[nt][1] - m_a);
            s[nt][2] = __expf(s[nt][2] - m_b);
            s[nt][3] = __expf(s[nt][3] - m_b);
            ra_ += s[nt][0] + s[nt][1];
            rb_ += s[nt][2] + s[nt][3];
        }
        ra_ += __shfl_xor_sync(0xffffffffu, ra_, 1);
        ra_ += __shfl_xor_sync(0xffffffffu, ra_, 2);
        rb_ += __shfl_xor_sync(0xffffffffu, rb_, 1);
        rb_ += __shfl_xor_sync(0xffffffffu, rb_, 2);
        l_a = l_a * corra + ra_;
        l_b = l_b * corrb + rb_;

#pragma unroll
        for (int nt = 0; nt < 8; nt++) {
            o[nt][0] *= corra; o[nt][1] *= corra;
            o[nt][2] *= corrb; o[nt][3] *= corrb;
        }

#pragma unroll
        for (int nt = 0; nt < 8; nt++) {
            *(uint2*)&Ps[w16 + r    ][nt * 8 + 2 * c] =
                make_uint2(f2tf32(s[nt][0]), f2tf32(s[nt][1]));
            *(uint2*)&Ps[w16 + r + 8][nt * 8 + 2 * c] =
                make_uint2(f2tf32(s[nt][2]), f2tf32(s[nt][3]));
        }
        __syncwarp();

#pragma unroll
        for (int ks = 0; ks < 8; ks++) {
            const int kk = ks * 8;
            unsigned a[4] = { Ps[w16 + r    ][kk + c    ],
                              Ps[w16 + r + 8][kk + c    ],
                              Ps[w16 + r    ][kk + c + 4],
                              Ps[w16 + r + 8][kk + c + 4] };
#pragma unroll
            for (int nt = 0; nt < 8; nt++) {
                unsigned bf[2] = { Vs[kk + c    ][nt * 8 + r],
                                   Vs[kk + c + 4][nt * 8 + r] };
                mma_tf32(o[nt], a, bf, o[nt]);
            }
        }
    }

    // Write O as tf32 bits (RNA) -> gemm_o consumes directly
    float ia = 1.0f / l_a, ib = 1.0f / l_b;
    size_t rowa = (size_t)(b * SEQ + q0 + w16 + r) * DIM + headoff;
#pragma unroll
    for (int nt = 0; nt < 8; nt++) {
        int col = nt * 8 + 2 * c;
        *(uint2*)(g_ao + rowa + col) =
            make_uint2(f2tf32(o[nt][0] * ia), f2tf32(o[nt][1] * ia));
        *(uint2*)(g_ao + rowa + 8 * DIM + col) =
            make_uint2(f2tf32(o[nt][2] * ib), f2tf32(o[nt][3] * ib));
    }
}

__global__ void __launch_bounds__(128) attn_kernel()
{
    extern __shared__ unsigned sm[];
    unsigned (*Qs)[68] = (unsigned(*)[68])(sm + SM_QS);
    unsigned (*Ks)[68] = (unsigned(*)[68])(sm + SM_KS);
    unsigned (*Vs)[72] = (unsigned(*)[72])(sm + SM_VS);
    unsigned (*Ps)[68] = (unsigned(*)[68])(sm + SM_PS);

    const int bh = blockIdx.y;
    const int b  = bh >> 4;
    const int h  = bh & 15;

    attn_one(blockIdx.x,      b, h, Qs, Ks, Vs, Ps);   // small tile (x <= 15)
    __syncthreads();
    attn_one(31 - blockIdx.x, b, h, Qs, Ks, Vs, Ps);   // large tile (>= 16)
}

// ---------------------------------------------------------------------------
extern "C" void kernel_launch(void* const* d_in, const int* in_sizes, int n_in,
                              void* d_out, int out_size)
{
    const float* Q  = (const float*)d_in[0];
    const float* K  = (const float*)d_in[1];
    const float* V  = (const float*)d_in[2];
    const float* Wq = (const float*)d_in[3];
    const float* Wk = (const float*)d_in[4];
    const float* Wv = (const float*)d_in[5];
    const float* Wo = (const float*)d_in[6];
    const float* bq = (const float*)d_in[7];
    const float* bk = (const float*)d_in[8];
    const float* bv = (const float*)d_in[9];
    const float* bo = (const float*)d_in[10];
    float* out = (float*)d_out;

    cudaFuncSetAttribute(attn_kernel, cudaFuncAttributeMaxDynamicSharedMemorySize,
                         SM_TOTAL_BYTES);
    cudaFuncSetAttribute(gemm_qkv_kernel, cudaFuncAttributeMaxDynamicSharedMemorySize,
                         GS_BYTES);
    cudaFuncSetAttribute(gemm_o_kernel, cudaFuncAttributeMaxDynamicSharedMemorySize,
                         GS_BYTES);

    preconvert_kernel<<<dim3(4096, 1, 7), 256>>>(Q, K, V, Wq, Wk, Wv, Wo);
    gemm_qkv_kernel<<<dim3(DIM / 128, MROWS / 128, 3), 128, GS_BYTES>>>(bq, bk, bv);
    rope_kernel<<<(MROWS * (DIM / 2)) / 256, 256>>>();
    attn_kernel<<<dim3(16, BATCH * HEADS), 128, SM_TOTAL_BYTES>>>();
    gemm_o_kernel<<<dim3(DIM / 128, MROWS / 128), 128, GS_BYTES>>>(bo, out);
}

// round 14
// speedup vs baseline: 17.1454x; 1.0532x over previous
#include <cuda_runtime.h>
#include <math.h>

#define BATCH 2
#define SEQ   2048
#define DIM   1024
#define HEADS 16
#define HD    64
#define MROWS (BATCH*SEQ)   // 4096

// Scratch. Referenced ONLY from device code.
__device__ float    g_qp[MROWS*DIM];    // tf32 bits after rope (q pre-scaled)
__device__ float    g_kp[MROWS*DIM];
__device__ float    g_vp[MROWS*DIM];
__device__ unsigned g_ao[MROWS*DIM];    // attention out, tf32 bits (RNA)
__device__ unsigned g_q32[MROWS*DIM];
__device__ unsigned g_k32[MROWS*DIM];
__device__ unsigned g_v32[MROWS*DIM];
__device__ unsigned g_w32[4][DIM*DIM];  // Wq, Wk, Wv, Wo

// ---------------------------------------------------------------------------
// tf32 + cp.async helpers (validated R9-R13)
// ---------------------------------------------------------------------------
__device__ __forceinline__ unsigned f2tf32(float x) {
    unsigned r;
    asm("cvt.rna.tf32.f32 %0, %1;" : "=r"(r) : "f"(x));
    return r;
}
__device__ __forceinline__ uint4 tf32x4(float4 v) {
    return make_uint4(f2tf32(v.x), f2tf32(v.y), f2tf32(v.z), f2tf32(v.w));
}
__device__ __forceinline__ void mma_tf32(float d[4], const unsigned a[4],
                                         const unsigned b[2], const float c[4]) {
    asm volatile(
        "mma.sync.aligned.m16n8k8.row.col.f32.tf32.tf32.f32 "
        "{%0,%1,%2,%3}, {%4,%5,%6,%7}, {%8,%9}, {%10,%11,%12,%13};"
        : "=f"(d[0]), "=f"(d[1]), "=f"(d[2]), "=f"(d[3])
        : "r"(a[0]), "r"(a[1]), "r"(a[2]), "r"(a[3]),
          "r"(b[0]), "r"(b[1]),
          "f"(c[0]), "f"(c[1]), "f"(c[2]), "f"(c[3]));
}
__device__ __forceinline__ void cp16(unsigned* smem_dst, const unsigned* gsrc) {
    unsigned daddr = (unsigned)__cvta_generic_to_shared(smem_dst);
    asm volatile("cp.async.cg.shared.global [%0], [%1], 16;"
                 :: "r"(daddr), "l"(gsrc) : "memory");
}
__device__ __forceinline__ void cp_commit() {
    asm volatile("cp.async.commit_group;" ::: "memory");
}
__device__ __forceinline__ void cp_wait0() {
    asm volatile("cp.async.wait_group 0;" ::: "memory");
}

// ---------------------------------------------------------------------------
// Pre-convert fp32 -> tf32(RNA) for all GEMM operands.
// ---------------------------------------------------------------------------
__global__ void __launch_bounds__(256) preconvert_kernel(
    const float* Q, const float* K, const float* V,
    const float* Wq, const float* Wk, const float* Wv, const float* Wo)
{
    const int z = blockIdx.z;
    const float* src; unsigned* dst; int nblk;
    switch (z) {
        case 0: src = Q;  dst = g_q32;    nblk = 4096; break;
        case 1: src = K;  dst = g_k32;    nblk = 4096; break;
        case 2: src = V;  dst = g_v32;    nblk = 4096; break;
        case 3: src = Wq; dst = g_w32[0]; nblk = 1024; break;
        case 4: src = Wk; dst = g_w32[1]; nblk = 1024; break;
        case 5: src = Wv; dst = g_w32[2]; nblk = 1024; break;
        default:src = Wo; dst = g_w32[3]; nblk = 1024; break;
    }
    if (blockIdx.x >= (unsigned)nblk) return;
    size_t i4 = ((size_t)blockIdx.x * 256 + threadIdx.x) * 4;
    float4 v = *(const float4*)(src + i4);
    *(uint4*)(dst + i4) = tf32x4(v);
}

// ---------------------------------------------------------------------------
// tf32 GEMM (validated R13): cp.async, double buffer, warp tile 64x64.
// ---------------------------------------------------------------------------
#define GS_AS0 0
#define GS_AS1 4608
#define GS_BS0 9216
#define GS_BS1 13568
#define GS_TOTAL_U32 17920
#define GS_BYTES (GS_TOTAL_U32*4)

__device__ __forceinline__ void gemm_stage(unsigned* As, unsigned* Bs,
                                           const unsigned* __restrict__ A32,
                                           const unsigned* __restrict__ W32,
                                           int row0, int col0, int k0, int tid)
{
#pragma unroll
    for (int i = 0; i < 8; i++) {
        int ch = tid + i * 128;
        int rr = ch >> 3;
        int cw = (ch & 7) << 2;
        cp16(As + rr * 36 + cw, A32 + (size_t)(row0 + rr) * DIM + k0 + cw);
    }
#pragma unroll
    for (int i = 0; i < 8; i++) {
        int ch = tid + i * 128;
        int rr = ch >> 5;
        int cw = (ch & 31) << 2;
        cp16(Bs + rr * 136 + cw, W32 + (size_t)(k0 + rr) * DIM + col0 + cw);
    }
    cp_commit();
}

__device__ __forceinline__ void gemm_tf32_body(const unsigned* __restrict__ A32,
                                               const unsigned* __restrict__ W32,
                                               const float* __restrict__ bias,
                                               float* __restrict__ C)
{
    extern __shared__ unsigned gsm[];

    const int tid  = threadIdx.x;
    const int lane = tid & 31;
    const int warp = tid >> 5;
    const int wm   = warp >> 1;
    const int wn   = warp & 1;
    const int r    = lane >> 2;
    const int c    = lane & 3;
    const int row0 = blockIdx.y * 128;
    const int col0 = blockIdx.x * 128;

    float acc[4][8][4];
#pragma unroll
    for (int mt = 0; mt < 4; mt++)
#pragma unroll
        for (int nt = 0; nt < 8; nt++)
#pragma unroll
            for (int e = 0; e < 4; e++) acc[mt][nt][e] = 0.0f;

    gemm_stage(gsm + GS_AS0, gsm + GS_BS0, A32, W32, row0, col0, 0, tid);
    cp_wait0();
    __syncthreads();

    for (int k0 = 0; k0 < DIM; k0 += 32) {
        const int cur = (k0 >> 5) & 1;
        unsigned* As = gsm + (cur ? GS_AS1 : GS_AS0);
        unsigned* Bs = gsm + (cur ? GS_BS1 : GS_BS0);
        const bool more = (k0 + 32 < DIM);

        if (more)
            gemm_stage(gsm + (cur ? GS_AS0 : GS_AS1), gsm + (cur ? GS_BS0 : GS_BS1),
                       A32, W32, row0, col0, k0 + 32, tid);

#pragma unroll
        for (int ks = 0; ks < 4; ks++) {
            const int kk = ks * 8;
            unsigned a[4][4], b[8][2];
#pragma unroll
            for (int mt = 0; mt < 4; mt++) {
                int m = wm * 64 + mt * 16;
                a[mt][0] = As[(m + r    ) * 36 + kk + c    ];
                a[mt][1] = As[(m + r + 8) * 36 + kk + c    ];
                a[mt][2] = As[(m + r    ) * 36 + kk + c + 4];
                a[mt][3] = As[(m + r + 8) * 36 + kk + c + 4];
            }
#pragma unroll
            for (int nt = 0; nt < 8; nt++) {
                int n = wn * 64 + nt * 8 + r;
                b[nt][0] = Bs[(kk + c    ) * 136 + n];
                b[nt][1] = Bs[(kk + c + 4) * 136 + n];
            }
#pragma unroll
            for (int mt = 0; mt < 4; mt++)
#pragma unroll
                for (int nt = 0; nt < 8; nt++)
                    mma_tf32(acc[mt][nt], a[mt], b[nt], acc[mt][nt]);
        }

        if (more) cp_wait0();
        __syncthreads();
    }

#pragma unroll
    for (int nt = 0; nt < 8; nt++) {
        int col = col0 + wn * 64 + nt * 8 + 2 * c;
        float b0 = bias[col], b1 = bias[col + 1];
#pragma unroll
        for (int mt = 0; mt < 4; mt++) {
            int row = row0 + wm * 64 + mt * 16 + r;
            float2 lo = make_float2(acc[mt][nt][0] + b0, acc[mt][nt][1] + b1);
            float2 hi = make_float2(acc[mt][nt][2] + b0, acc[mt][nt][3] + b1);
            *(float2*)(C + (size_t)row * DIM + col)       = lo;
            *(float2*)(C + (size_t)(row + 8) * DIM + col) = hi;
        }
    }
}

__global__ void __launch_bounds__(128) gemm_qkv_kernel(
    const float* bq, const float* bk, const float* bv)
{
    if (blockIdx.z == 0)      gemm_tf32_body(g_q32, g_w32[0], bq, g_qp);
    else if (blockIdx.z == 1) gemm_tf32_body(g_k32, g_w32[1], bk, g_kp);
    else                      gemm_tf32_body(g_v32, g_w32[2], bv, g_vp);
}

__global__ void __launch_bounds__(128) gemm_o_kernel(const float* bo, float* C)
{
    gemm_tf32_body(g_ao, g_w32[3], bo, C);
}

// ---------------------------------------------------------------------------
// RoPE + tf32 pre-conversion in place (validated R12/R13).
// ---------------------------------------------------------------------------
__global__ void __launch_bounds__(256) rope_kernel()
{
    int idx = blockIdx.x * blockDim.x + threadIdx.x;
    if (idx >= MROWS * (DIM / 2)) return;
    int m = idx >> 9;
    int cc = idx & 511;
    int h = cc >> 5;
    int d = cc & 31;
    int pos = m & (SEQ - 1);

    float invf = 1.0f / powf(10000.0f, (float)d * (1.0f / 32.0f));
    float ang  = (float)pos * invf;
    float cs, sn;
    sincosf(ang, &cs, &sn);

    int base = m * DIM + h * HD + d;
    unsigned* qo = (unsigned*)g_qp;
    unsigned* ko = (unsigned*)g_kp;
    unsigned* vo = (unsigned*)g_vp;

    float q1 = g_qp[base], q2 = g_qp[base + 32];
    qo[base]      = f2tf32((q1 * cs + q2 * sn) * 0.125f);
    qo[base + 32] = f2tf32((q2 * cs - q1 * sn) * 0.125f);
    float k1 = g_kp[base], k2 = g_kp[base + 32];
    ko[base]      = f2tf32(k1 * cs + k2 * sn);
    ko[base + 32] = f2tf32(k2 * cs - k1 * sn);
    float v1 = g_vp[base], v2 = g_vp[base + 32];
    vo[base]      = f2tf32(v1);
    vo[base + 32] = f2tf32(v2);
}

// ---------------------------------------------------------------------------
// tf32 flash attention with cp.async DOUBLE-BUFFERED K/V (this round's change)
// + balanced pairing (CTA x -> tiles {x, 31-x}). Grid (16, 32), 128 threads.
// Smem u32 layout: Qs[64][68] | Ks0 | Ks1 [64][68] | Vs0 | Vs1 [64][72] | Ps[64][68]
// ---------------------------------------------------------------------------
#define AQ  0
#define AK0 4352
#define AK1 8704
#define AV0 13056
#define AV1 17664
#define AP  22272
#define SM_TOTAL_U32 26624
#define SM_TOTAL_BYTES (SM_TOTAL_U32*4)

__device__ __forceinline__ void attn_stage_kv(unsigned* Kd, unsigned* Vd,
                                              const unsigned* ksrc, const unsigned* vsrc,
                                              int b, int k0, size_t headoff, int tid)
{
#pragma unroll
    for (int i = 0; i < 8; i++) {
        int ch = tid + i * 128;
        int rr = ch >> 4;
        int c4 = (ch & 15) * 4;
        size_t g = (size_t)(b * SEQ + k0 + rr) * DIM + headoff + c4;
        cp16(Kd + rr * 68 + c4, ksrc + g);
        cp16(Vd + rr * 72 + c4, vsrc + g);
    }
    cp_commit();
}

__device__ __forceinline__ void attn_one(int qt, int b, int h, unsigned* sm)
{
    const int tid  = threadIdx.x;
    const int lane = tid & 31;
    const int warp = tid >> 5;
    const int r    = lane >> 2;
    const int c    = lane & 3;
    const int w16  = warp * 16;
    const int q0   = qt * 64;
    const size_t headoff = (size_t)h * HD;

    unsigned (*Qs)[68] = (unsigned(*)[68])(sm + AQ);
    unsigned (*Ps)[68] = (unsigned(*)[68])(sm + AP);

    const unsigned* qsrc = (const unsigned*)g_qp;
    const unsigned* ksrc = (const unsigned*)g_kp;
    const unsigned* vsrc = (const unsigned*)g_vp;

    __syncthreads();   // prior tile's reads of Qs / K/V buffers complete

    // Issue first K/V stage, then fill Q via regular stores (covered by the
    // wait+sync at loop iteration 0).
    attn_stage_kv(sm + AK0, sm + AV0, ksrc, vsrc, b, 0, headoff, tid);
#pragma unroll
    for (int i = 0; i < 8; i++) {
        int idx = tid + i * 128;
        int rr  = idx >> 4;
        int c4  = (idx & 15) * 4;
        *(uint4*)&Qs[rr][c4] =
            *(const uint4*)(qsrc + (size_t)(b * SEQ + q0 + rr) * DIM + headoff + c4);
    }

    float o[8][4];
#pragma unroll
    for (int nt = 0; nt < 8; nt++)
#pragma unroll
        for (int e = 0; e < 4; e++) o[nt][e] = 0.0f;
    float m_a = -1e30f, m_b = -1e30f, l_a = 0.0f, l_b = 0.0f;

    for (int jt = 0; jt <= qt; jt++) {
        const int cur = jt & 1;
        unsigned (*Ks)[68] = (unsigned(*)[68])(sm + (cur ? AK1 : AK0));
        unsigned (*Vs)[72] = (unsigned(*)[72])(sm + (cur ? AV1 : AV0));

        cp_wait0();
        __syncthreads();   // cur buffers ready; prev compute done (buffer-reuse safe)

        if (jt < qt)
            attn_stage_kv(sm + (cur ? AK0 : AK1), sm + (cur ? AV0 : AV1),
                          ksrc, vsrc, b, (jt + 1) * 64, headoff, tid);

        // S = Q @ K^T
        float s[8][4];
#pragma unroll
        for (int nt = 0; nt < 8; nt++)
#pragma unroll
            for (int e = 0; e < 4; e++) s[nt][e] = 0.0f;

#pragma unroll
        for (int ks = 0; ks < 8; ks++) {
            const int kk = ks * 8;
            unsigned a[4] = { Qs[w16 + r    ][kk + c    ],
                              Qs[w16 + r + 8][kk + c    ],
                              Qs[w16 + r    ][kk + c + 4],
                              Qs[w16 + r + 8][kk + c + 4] };
#pragma unroll
            for (int nt = 0; nt < 8; nt++) {
                unsigned bf[2] = { Ks[nt * 8 + r][kk + c    ],
                                   Ks[nt * 8 + r][kk + c + 4] };
                mma_tf32(s[nt], a, bf, s[nt]);
            }
        }

        if (jt == qt) {
            const int ra = w16 + r, rb = ra + 8;
#pragma unroll
            for (int nt = 0; nt < 8; nt++) {
                int c0_ = nt * 8 + 2 * c;
                if (c0_     > ra) s[nt][0] = -1e30f;
                if (c0_ + 1 > ra) s[nt][1] = -1e30f;
                if (c0_     > rb) s[nt][2] = -1e30f;
                if (c0_ + 1 > rb) s[nt][3] = -1e30f;
            }
        }

        float mxa = -1e30f, mxb = -1e30f;
#pragma unroll
        for (int nt = 0; nt < 8; nt++) {
            mxa = fmaxf(mxa, fmaxf(s[nt][0], s[nt][1]));
            mxb = fmaxf(mxb, fmaxf(s[nt][2], s[nt][3]));
        }
        mxa = fmaxf(mxa, __shfl_xor_sync(0xffffffffu, mxa, 1));
        mxa = fmaxf(mxa, __shfl_xor_sync(0xffffffffu, mxa, 2));
        mxb = fmaxf(mxb, __shfl_xor_sync(0xffffffffu, mxb, 1));
        mxb = fmaxf(mxb, __shfl_xor_sync(0xffffffffu, mxb, 2));

        float mna = fmaxf(m_a, mxa), mnb = fmaxf(m_b, mxb);
        float corra = __expf(m_a - mna), corrb = __expf(m_b - mnb);
        m_a = mna; m_b = mnb;

        float ra_ = 0.0f, rb_ = 0.0f;
#pragma unroll
        for (int nt = 0; nt < 8; nt++) {
            s[nt][0] = __expf(s[nt][0] - m_a);
            s[nt][1] = __expf(s[nt][1] - m_a);
            s[nt][2] = __expf(s[nt][2] - m_b);
            s[nt][3] = __expf(s[nt][3] - m_b);
            ra_ += s[nt][0] + s[nt][1];
            rb_ += s[nt][2] + s[nt][3];
        }
        ra_ += __shfl_xor_sync(0xffffffffu, ra_, 1);
        ra_ += __shfl_xor_sync(0xffffffffu, ra_, 2);
        rb_ += __shfl_xor_sync(0xffffffffu, rb_, 1);
        rb_ += __shfl_xor_sync(0xffffffffu, rb_, 2);
        l_a = l_a * corra + ra_;
        l_b = l_b * corrb + rb_;

#pragma unroll
        for (int nt = 0; nt < 8; nt++) {
            o[nt][0] *= corra; o[nt][1] *= corra;
            o[nt][2] *= corrb; o[nt][3] *= corrb;
        }

        // P -> smem (own warp rows only; PV a-frags read only own rows)
#pragma unroll
        for (int nt = 0; nt < 8; nt++) {
            *(uint2*)&Ps[w16 + r    ][nt * 8 + 2 * c] =
                make_uint2(f2tf32(s[nt][0]), f2tf32(s[nt][1]));
            *(uint2*)&Ps[w16 + r + 8][nt * 8 + 2 * c] =
                make_uint2(f2tf32(s[nt][2]), f2tf32(s[nt][3]));
        }
        __syncwarp();

        // O += P @ V
#pragma unroll
        for (int ks = 0; ks < 8; ks++) {
            const int kk = ks * 8;
            unsigned a[4] = { Ps[w16 + r    ][kk + c    ],
                              Ps[w16 + r + 8][kk + c    ],
                              Ps[w16 + r    ][kk + c + 4],
                              Ps[w16 + r + 8][kk + c + 4] };
#pragma unroll
            for (int nt = 0; nt < 8; nt++) {
                unsigned bf[2] = { Vs[kk + c    ][nt * 8 + r],
                                   Vs[kk + c + 4][nt * 8 + r] };
                mma_tf32(o[nt], a, bf, o[nt]);
            }
        }
    }

    float ia = 1.0f / l_a, ib = 1.0f / l_b;
    size_t rowa = (size_t)(b * SEQ + q0 + w16 + r) * DIM + headoff;
#pragma unroll
    for (int nt = 0; nt < 8; nt++) {
        int col = nt * 8 + 2 * c;
        *(uint2*)(g_ao + rowa + col) =
            make_uint2(f2tf32(o[nt][0] * ia), f2tf32(o[nt][1] * ia));
        *(uint2*)(g_ao + rowa + 8 * DIM + col) =
            make_uint2(f2tf32(o[nt][2] * ib), f2tf32(o[nt][3] * ib));
    }
}

__global__ void __launch_bounds__(128) attn_kernel()
{
    extern __shared__ unsigned sm[];
    const int bh = blockIdx.y;
    const int b  = bh >> 4;
    const int h  = bh & 15;

    attn_one(blockIdx.x,      b, h, sm);
    attn_one(31 - blockIdx.x, b, h, sm);
}

// ---------------------------------------------------------------------------
extern "C" void kernel_launch(void* const* d_in, const int* in_sizes, int n_in,
                              void* d_out, int out_size)
{
    const float* Q  = (const float*)d_in[0];
    const float* K  = (const float*)d_in[1];
    const float* V  = (const float*)d_in[2];
    const float* Wq = (const float*)d_in[3];
    const float* Wk = (const float*)d_in[4];
    const float* Wv = (const float*)d_in[5];
    const float* Wo = (const float*)d_in[6];
    const float* bq = (const float*)d_in[7];
    const float* bk = (const float*)d_in[8];
    const float* bv = (const float*)d_in[9];
    const float* bo = (const float*)d_in[10];
    float* out = (float*)d_out;

    cudaFuncSetAttribute(attn_kernel, cudaFuncAttributeMaxDynamicSharedMemorySize,
                         SM_TOTAL_BYTES);
    cudaFuncSetAttribute(gemm_qkv_kernel, cudaFuncAttributeMaxDynamicSharedMemorySize,
                         GS_BYTES);
    cudaFuncSetAttribute(gemm_o_kernel, cudaFuncAttributeMaxDynamicSharedMemorySize,
                         GS_BYTES);

    preconvert_kernel<<<dim3(4096, 1, 7), 256>>>(Q, K, V, Wq, Wk, Wv, Wo);
    gemm_qkv_kernel<<<dim3(DIM / 128, MROWS / 128, 3), 128, GS_BYTES>>>(bq, bk, bv);
    rope_kernel<<<(MROWS * (DIM / 2)) / 256, 256>>>();
    attn_kernel<<<dim3(16, BATCH * HEADS), 128, SM_TOTAL_BYTES>>>();
    gemm_o_kernel<<<dim3(DIM / 128, MROWS / 128), 128, GS_BYTES>>>(bo, out);
}

// round 16
// speedup vs baseline: 20.9013x; 1.2191x over previous
#include <cuda_runtime.h>
#include <cuda_fp16.h>
#include <math.h>

#define BATCH 2
#define SEQ   2048
#define DIM   1024
#define HEADS 16
#define HD    64
#define MROWS (BATCH*SEQ)   // 4096

// Scratch. Referenced ONLY from device code.
__device__ float    g_qp[MROWS*DIM];    // fp32 projections (rope input)
__device__ float    g_kp[MROWS*DIM];
__device__ float    g_vp[MROWS*DIM];
__device__ unsigned g_ao[MROWS*DIM];    // attention out, tf32 bits (RNA)
__device__ unsigned g_q32[MROWS*DIM];
__device__ unsigned g_k32[MROWS*DIM];
__device__ unsigned g_v32[MROWS*DIM];
__device__ unsigned g_w32[4][DIM*DIM];  // Wq, Wk, Wv, Wo
// fp16 attention operands:
__device__ __half   g_qh[MROWS*DIM];    // rope(q)*0.125, fp16
__device__ __half   g_kh[MROWS*DIM];    // rope(k), fp16
__device__ __half2  g_vph[BATCH*HEADS*(SEQ/2)*HD];  // V packed (v[2k],v[2k+1])

// ---------------------------------------------------------------------------
// helpers
// ---------------------------------------------------------------------------
__device__ __forceinline__ unsigned f2tf32(float x) {
    unsigned r;
    asm("cvt.rna.tf32.f32 %0, %1;" : "=r"(r) : "f"(x));
    return r;
}
__device__ __forceinline__ uint4 tf32x4(float4 v) {
    return make_uint4(f2tf32(v.x), f2tf32(v.y), f2tf32(v.z), f2tf32(v.w));
}
__device__ __forceinline__ unsigned h2_u32(__half2 h) {
    union { __half2 h2; unsigned u; } cv;
    cv.h2 = h;
    return cv.u;
}
__device__ __forceinline__ void mma_tf32(float d[4], const unsigned a[4],
                                         const unsigned b[2], const float c[4]) {
    asm volatile(
        "mma.sync.aligned.m16n8k8.row.col.f32.tf32.tf32.f32 "
        "{%0,%1,%2,%3}, {%4,%5,%6,%7}, {%8,%9}, {%10,%11,%12,%13};"
        : "=f"(d[0]), "=f"(d[1]), "=f"(d[2]), "=f"(d[3])
        : "r"(a[0]), "r"(a[1]), "r"(a[2]), "r"(a[3]),
          "r"(b[0]), "r"(b[1]),
          "f"(c[0]), "f"(c[1]), "f"(c[2]), "f"(c[3]));
}
__device__ __forceinline__ void mma_f16(float d[4], const unsigned a[4],
                                        const unsigned b[2], const float c[4]) {
    asm volatile(
        "mma.sync.aligned.m16n8k16.row.col.f32.f16.f16.f32 "
        "{%0,%1,%2,%3}, {%4,%5,%6,%7}, {%8,%9}, {%10,%11,%12,%13};"
        : "=f"(d[0]), "=f"(d[1]), "=f"(d[2]), "=f"(d[3])
        : "r"(a[0]), "r"(a[1]), "r"(a[2]), "r"(a[3]),
          "r"(b[0]), "r"(b[1]),
          "f"(c[0]), "f"(c[1]), "f"(c[2]), "f"(c[3]));
}
__device__ __forceinline__ void cp16(unsigned* smem_dst, const unsigned* gsrc) {
    unsigned daddr = (unsigned)__cvta_generic_to_shared(smem_dst);
    asm volatile("cp.async.cg.shared.global [%0], [%1], 16;"
                 :: "r"(daddr), "l"(gsrc) : "memory");
}
__device__ __forceinline__ void cp_commit() {
    asm volatile("cp.async.commit_group;" ::: "memory");
}
__device__ __forceinline__ void cp_wait0() {
    asm volatile("cp.async.wait_group 0;" ::: "memory");
}

// ---------------------------------------------------------------------------
// Pre-convert fp32 -> tf32(RNA) for GEMM operands (validated).
// ---------------------------------------------------------------------------
__global__ void __launch_bounds__(256) preconvert_kernel(
    const float* Q, const float* K, const float* V,
    const float* Wq, const float* Wk, const float* Wv, const float* Wo)
{
    const int z = blockIdx.z;
    const float* src; unsigned* dst; int nblk;
    switch (z) {
        case 0: src = Q;  dst = g_q32;    nblk = 4096; break;
        case 1: src = K;  dst = g_k32;    nblk = 4096; break;
        case 2: src = V;  dst = g_v32;    nblk = 4096; break;
        case 3: src = Wq; dst = g_w32[0]; nblk = 1024; break;
        case 4: src = Wk; dst = g_w32[1]; nblk = 1024; break;
        case 5: src = Wv; dst = g_w32[2]; nblk = 1024; break;
        default:src = Wo; dst = g_w32[3]; nblk = 1024; break;
    }
    if (blockIdx.x >= (unsigned)nblk) return;
    size_t i4 = ((size_t)blockIdx.x * 256 + threadIdx.x) * 4;
    float4 v = *(const float4*)(src + i4);
    *(uint4*)(dst + i4) = tf32x4(v);
}

// ---------------------------------------------------------------------------
// tf32 GEMM (validated R13/R14): cp.async, double buffer, warp tile 64x64.
// ---------------------------------------------------------------------------
#define GS_AS0 0
#define GS_AS1 4608
#define GS_BS0 9216
#define GS_BS1 13568
#define GS_TOTAL_U32 17920
#define GS_BYTES (GS_TOTAL_U32*4)

__device__ __forceinline__ void gemm_stage(unsigned* As, unsigned* Bs,
                                           const unsigned* __restrict__ A32,
                                           const unsigned* __restrict__ W32,
                                           int row0, int col0, int k0, int tid)
{
#pragma unroll
    for (int i = 0; i < 8; i++) {
        int ch = tid + i * 128;
        int rr = ch >> 3;
        int cw = (ch & 7) << 2;
        cp16(As + rr * 36 + cw, A32 + (size_t)(row0 + rr) * DIM + k0 + cw);
    }
#pragma unroll
    for (int i = 0; i < 8; i++) {
        int ch = tid + i * 128;
        int rr = ch >> 5;
        int cw = (ch & 31) << 2;
        cp16(Bs + rr * 136 + cw, W32 + (size_t)(k0 + rr) * DIM + col0 + cw);
    }
    cp_commit();
}

__device__ __forceinline__ void gemm_tf32_body(const unsigned* __restrict__ A32,
                                               const unsigned* __restrict__ W32,
                                               const float* __restrict__ bias,
                                               float* __restrict__ C)
{
    extern __shared__ unsigned gsm[];

    const int tid  = threadIdx.x;
    const int lane = tid & 31;
    const int warp = tid >> 5;
    const int wm   = warp >> 1;
    const int wn   = warp & 1;
    const int r    = lane >> 2;
    const int c    = lane & 3;
    const int row0 = blockIdx.y * 128;
    const int col0 = blockIdx.x * 128;

    float acc[4][8][4];
#pragma unroll
    for (int mt = 0; mt < 4; mt++)
#pragma unroll
        for (int nt = 0; nt < 8; nt++)
#pragma unroll
            for (int e = 0; e < 4; e++) acc[mt][nt][e] = 0.0f;

    gemm_stage(gsm + GS_AS0, gsm + GS_BS0, A32, W32, row0, col0, 0, tid);
    cp_wait0();
    __syncthreads();

    for (int k0 = 0; k0 < DIM; k0 += 32) {
        const int cur = (k0 >> 5) & 1;
        unsigned* As = gsm + (cur ? GS_AS1 : GS_AS0);
        unsigned* Bs = gsm + (cur ? GS_BS1 : GS_BS0);
        const bool more = (k0 + 32 < DIM);

        if (more)
            gemm_stage(gsm + (cur ? GS_AS0 : GS_AS1), gsm + (cur ? GS_BS0 : GS_BS1),
                       A32, W32, row0, col0, k0 + 32, tid);

#pragma unroll
        for (int ks = 0; ks < 4; ks++) {
            const int kk = ks * 8;
            unsigned a[4][4], b[8][2];
#pragma unroll
            for (int mt = 0; mt < 4; mt++) {
                int m = wm * 64 + mt * 16;
                a[mt][0] = As[(m + r    ) * 36 + kk + c    ];
                a[mt][1] = As[(m + r + 8) * 36 + kk + c    ];
                a[mt][2] = As[(m + r    ) * 36 + kk + c + 4];
                a[mt][3] = As[(m + r + 8) * 36 + kk + c + 4];
            }
#pragma unroll
            for (int nt = 0; nt < 8; nt++) {
                int n = wn * 64 + nt * 8 + r;
                b[nt][0] = Bs[(kk + c    ) * 136 + n];
                b[nt][1] = Bs[(kk + c + 4) * 136 + n];
            }
#pragma unroll
            for (int mt = 0; mt < 4; mt++)
#pragma unroll
                for (int nt = 0; nt < 8; nt++)
                    mma_tf32(acc[mt][nt], a[mt], b[nt], acc[mt][nt]);
        }

        if (more) cp_wait0();
        __syncthreads();
    }

#pragma unroll
    for (int nt = 0; nt < 8; nt++) {
        int col = col0 + wn * 64 + nt * 8 + 2 * c;
        float b0 = bias[col], b1 = bias[col + 1];
#pragma unroll
        for (int mt = 0; mt < 4; mt++) {
            int row = row0 + wm * 64 + mt * 16 + r;
            float2 lo = make_float2(acc[mt][nt][0] + b0, acc[mt][nt][1] + b1);
            float2 hi = make_float2(acc[mt][nt][2] + b0, acc[mt][nt][3] + b1);
            *(float2*)(C + (size_t)row * DIM + col)       = lo;
            *(float2*)(C + (size_t)(row + 8) * DIM + col) = hi;
        }
    }
}

__global__ void __launch_bounds__(128) gemm_qkv_kernel(
    const float* bq, const float* bk, const float* bv)
{
    if (blockIdx.z == 0)      gemm_tf32_body(g_q32, g_w32[0], bq, g_qp);
    else if (blockIdx.z == 1) gemm_tf32_body(g_k32, g_w32[1], bk, g_kp);
    else                      gemm_tf32_body(g_v32, g_w32[2], bv, g_vp);
}

__global__ void __launch_bounds__(128) gemm_o_kernel(const float* bo, float* C)
{
    gemm_tf32_body(g_ao, g_w32[3], bo, C);
}

// ---------------------------------------------------------------------------
// RoPE -> fp16 (q pre-scaled by 1/8). Rotation direction validated R7+.
// ---------------------------------------------------------------------------
__global__ void __launch_bounds__(256) rope_kernel()
{
    int idx = blockIdx.x * blockDim.x + threadIdx.x;
    if (idx >= MROWS * (DIM / 2)) return;
    int m = idx >> 9;
    int cc = idx & 511;
    int h = cc >> 5;
    int d = cc & 31;
    int pos = m & (SEQ - 1);

    float invf = 1.0f / powf(10000.0f, (float)d * (1.0f / 32.0f));
    float ang  = (float)pos * invf;
    float cs, sn;
    sincosf(ang, &cs, &sn);

    int base = m * DIM + h * HD + d;
    float q1 = g_qp[base], q2 = g_qp[base + 32];
    g_qh[base]      = __float2half_rn((q1 * cs + q2 * sn) * 0.125f);
    g_qh[base + 32] = __float2half_rn((q2 * cs - q1 * sn) * 0.125f);
    float k1 = g_kp[base], k2 = g_kp[base + 32];
    g_kh[base]      = __float2half_rn(k1 * cs + k2 * sn);
    g_kh[base + 32] = __float2half_rn(k2 * cs - k1 * sn);
}

// ---------------------------------------------------------------------------
// Pack V into fp16 half2 pairs along the key dim:
// g_vph[bh][l2][d] = (v[2*l2][d], v[2*l2+1][d])
// ---------------------------------------------------------------------------
__global__ void __launch_bounds__(256) packv_kernel()
{
    int idx = blockIdx.x * 256 + threadIdx.x;   // 2,097,152 total
    int d  = idx & 63;
    int l2 = (idx >> 6) & 1023;
    int bh = idx >> 16;
    int b  = bh >> 4;
    int h  = bh & 15;
    size_t g0 = (size_t)(b * SEQ + 2 * l2) * DIM + h * HD + d;
    float v0 = g_vp[g0];
    float v1 = g_vp[g0 + DIM];
    g_vph[idx] = __floats2half2_rn(v0, v1);
}

// ---------------------------------------------------------------------------
// fp16 tensor-core causal flash attention (fp32 softmax/accum).
// Grid (16, 32); 128 threads, 4 warps; CTA x -> q-tiles {x, 31-x}.
// Smem u32: Qs[64][36] | Ks0,Ks1[64][36] | Vs0,Vs1[32][72] | Ps[64][36]
//  = 13824 u32 = 55296 B  -> 3 CTAs/SM.
// Frag banks: Q/K/P stride 36 -> 4r+c (unique); Vpack stride 72 -> 8c+r (unique).
// ---------------------------------------------------------------------------
#define AQ  0
#define AK0 2304
#define AK1 4608
#define AV0 6912
#define AV1 9216
#define AP  11520
#define SM_TOTAL_U32 13824
#define SM_TOTAL_BYTES (SM_TOTAL_U32*4)

__device__ __forceinline__ void attn_stage_kv(unsigned* Kd, unsigned* Vd,
                                              int b, int h, int k0, int tid)
{
    const unsigned* ku32 = (const unsigned*)g_kh;
    const unsigned* vu32 = (const unsigned*)g_vph;
#pragma unroll
    for (int i = 0; i < 4; i++) {              // K: 64 rows x 8 chunks
        int ch = tid + i * 128;
        int rr = ch >> 3;
        int cw = (ch & 7) << 2;
        cp16(Kd + rr * 36 + cw,
             ku32 + (size_t)(b * SEQ + k0 + rr) * 512 + h * 32 + cw);
    }
#pragma unroll
    for (int i = 0; i < 4; i++) {              // V: 32 half2-rows x 16 chunks
        int ch = tid + i * 128;
        int rr = ch >> 4;
        int cw = (ch & 15) << 2;
        cp16(Vd + rr * 72 + cw,
             vu32 + ((size_t)(b * HEADS + h) * 1024 + (k0 >> 1) + rr) * 64 + cw);
    }
    cp_commit();
}

__device__ __forceinline__ void attn_one(int qt, int b, int h, unsigned* sm)
{
    const int tid  = threadIdx.x;
    const int lane = tid & 31;
    const int warp = tid >> 5;
    const int r    = lane >> 2;
    const int c    = lane & 3;
    const int w16  = warp * 16;
    const int q0   = qt * 64;

    unsigned* Qs = sm + AQ;
    unsigned* Ps = sm + AP;
    const unsigned* qu32 = (const unsigned*)g_qh;

    __syncthreads();   // prior tile fully done (buffers reusable)

    attn_stage_kv(sm + AK0, sm + AV0, b, h, 0, tid);
#pragma unroll
    for (int i = 0; i < 4; i++) {              // Q: 64 rows x 8 chunks
        int ch = tid + i * 128;
        int rr = ch >> 3;
        int cw = (ch & 7) << 2;
        cp16(Qs + rr * 36 + cw,
             qu32 + (size_t)(b * SEQ + q0 + rr) * 512 + h * 32 + cw);
    }
    cp_commit();
    cp_wait0();
    __syncthreads();

    // Hoist loop-invariant Q fragments
    unsigned qa[4][4];
#pragma unroll
    for (int ks = 0; ks < 4; ks++) {
        const int kk = ks * 8;
        qa[ks][0] = Qs[(w16 + r    ) * 36 + kk + c    ];
        qa[ks][1] = Qs[(w16 + r + 8) * 36 + kk + c    ];
        qa[ks][2] = Qs[(w16 + r    ) * 36 + kk + c + 4];
        qa[ks][3] = Qs[(w16 + r + 8) * 36 + kk + c + 4];
    }

    float o[8][4];
#pragma unroll
    for (int nt = 0; nt < 8; nt++)
#pragma unroll
        for (int e = 0; e < 4; e++) o[nt][e] = 0.0f;
    float m_a = -1e30f, m_b = -1e30f, l_a = 0.0f, l_b = 0.0f;

    for (int jt = 0; jt <= qt; jt++) {
        const int cur = jt & 1;
        unsigned* Ks = sm + (cur ? AK1 : AK0);
        unsigned* Vs = sm + (cur ? AV1 : AV0);

        if (jt < qt)
            attn_stage_kv(sm + (cur ? AK0 : AK1), sm + (cur ? AV0 : AV1),
                          b, h, (jt + 1) * 64, tid);

        // S = Q @ K^T  (32 mma, k16)
        float s[8][4];
#pragma unroll
        for (int nt = 0; nt < 8; nt++)
#pragma unroll
            for (int e = 0; e < 4; e++) s[nt][e] = 0.0f;

#pragma unroll
        for (int ks = 0; ks < 4; ks++) {
            const int kk = ks * 8;
#pragma unroll
            for (int nt = 0; nt < 8; nt++) {
                unsigned bf[2] = { Ks[(nt * 8 + r) * 36 + kk + c    ],
                                   Ks[(nt * 8 + r) * 36 + kk + c + 4] };
                mma_f16(s[nt], qa[ks], bf, s[nt]);
            }
        }

        if (jt == qt) {
            const int ra = w16 + r, rb = ra + 8;
#pragma unroll
            for (int nt = 0; nt < 8; nt++) {
                int c0_ = nt * 8 + 2 * c;
                if (c0_     > ra) s[nt][0] = -1e30f;
                if (c0_ + 1 > ra) s[nt][1] = -1e30f;
                if (c0_     > rb) s[nt][2] = -1e30f;
                if (c0_ + 1 > rb) s[nt][3] = -1e30f;
            }
        }

        // Online softmax (fp32; rows spread over quad lanes -> shfl xor 1,2)
        float mxa = -1e30f, mxb = -1e30f;
#pragma unroll
        for (int nt = 0; nt < 8; nt++) {
            mxa = fmaxf(mxa, fmaxf(s[nt][0], s[nt][1]));
            mxb = fmaxf(mxb, fmaxf(s[nt][2], s[nt][3]));
        }
        mxa = fmaxf(mxa, __shfl_xor_sync(0xffffffffu, mxa, 1));
        mxa = fmaxf(mxa, __shfl_xor_sync(0xffffffffu, mxa, 2));
        mxb = fmaxf(mxb, __shfl_xor_sync(0xffffffffu, mxb, 1));
        mxb = fmaxf(mxb, __shfl_xor_sync(0xffffffffu, mxb, 2));

        float mna = fmaxf(m_a, mxa), mnb = fmaxf(m_b, mxb);
        float corra = __expf(m_a - mna), corrb = __expf(m_b - mnb);
        m_a = mna; m_b = mnb;

        float ra_ = 0.0f, rb_ = 0.0f;
#pragma unroll
        for (int nt = 0; nt < 8; nt++) {
            s[nt][0] = __expf(s[nt][0] - m_a);
            s[nt][1] = __expf(s[nt][1] - m_a);
            s[nt][2] = __expf(s[nt][2] - m_b);
            s[nt][3] = __expf(s[nt][3] - m_b);
            ra_ += s[nt][0] + s[nt][1];
            rb_ += s[nt][2] + s[nt][3];
        }
        ra_ += __shfl_xor_sync(0xffffffffu, ra_, 1);
        ra_ += __shfl_xor_sync(0xffffffffu, ra_, 2);
        rb_ += __shfl_xor_sync(0xffffffffu, rb_, 1);
        rb_ += __shfl_xor_sync(0xffffffffu, rb_, 2);
        l_a = l_a * corra + ra_;
        l_b = l_b * corrb + rb_;

#pragma unroll
        for (int nt = 0; nt < 8; nt++) {
            o[nt][0] *= corra; o[nt][1] *= corra;
            o[nt][2] *= corrb; o[nt][3] *= corrb;
        }

        // P -> fp16 -> smem (own warp rows only)
#pragma unroll
        for (int nt = 0; nt < 8; nt++) {
            Ps[(w16 + r    ) * 36 + 4 * nt + c] =
                h2_u32(__floats2half2_rn(s[nt][0], s[nt][1]));
            Ps[(w16 + r + 8) * 36 + 4 * nt + c] =
                h2_u32(__floats2half2_rn(s[nt][2], s[nt][3]));
        }
        __syncwarp();

        // O += P @ V  (32 mma, k16)
#pragma unroll
        for (int ks = 0; ks < 4; ks++) {
            const int kk  = ks * 8;   // P word offset
            unsigned a[4] = { Ps[(w16 + r    ) * 36 + kk + c    ],
                              Ps[(w16 + r + 8) * 36 + kk + c    ],
                              Ps[(w16 + r    ) * 36 + kk + c + 4],
                              Ps[(w16 + r + 8) * 36 + kk + c + 4] };
#pragma unroll
            for (int nt = 0; nt < 8; nt++) {
                unsigned bf[2] = { Vs[(kk + c    ) * 72 + nt * 8 + r],
                                   Vs[(kk + c + 4) * 72 + nt * 8 + r] };
                mma_f16(o[nt], a, bf, o[nt]);
            }
        }

        if (jt < qt) { cp_wait0(); __syncthreads(); }
    }

    float ia = 1.0f / l_a, ib = 1.0f / l_b;
    size_t rowa = (size_t)(b * SEQ + q0 + w16 + r) * DIM + (size_t)h * HD;
#pragma unroll
    for (int nt = 0; nt < 8; nt++) {
        int col = nt * 8 + 2 * c;
        *(uint2*)(g_ao + rowa + col) =
            make_uint2(f2tf32(o[nt][0] * ia), f2tf32(o[nt][1] * ia));
        *(uint2*)(g_ao + rowa + 8 * DIM + col) =
            make_uint2(f2tf32(o[nt][2] * ib), f2tf32(o[nt][3] * ib));
    }
}

__global__ void __launch_bounds__(128, 3) attn_kernel()
{
    extern __shared__ unsigned sm[];
    const int bh = blockIdx.y;
    const int b  = bh >> 4;
    const int h  = bh & 15;

    attn_one(blockIdx.x,      b, h, sm);
    attn_one(31 - blockIdx.x, b, h, sm);
}

// ---------------------------------------------------------------------------
extern "C" void kernel_launch(void* const* d_in, const int* in_sizes, int n_in,
                              void* d_out, int out_size)
{
    const float* Q  = (const float*)d_in[0];
    const float* K  = (const float*)d_in[1];
    const float* V  = (const float*)d_in[2];
    const float* Wq = (const float*)d_in[3];
    const float* Wk = (const float*)d_in[4];
    const float* Wv = (const float*)d_in[5];
    const float* Wo = (const float*)d_in[6];
    const float* bq = (const float*)d_in[7];
    const float* bk = (const float*)d_in[8];
    const float* bv = (const float*)d_in[9];
    const float* bo = (const float*)d_in[10];
    float* out = (float*)d_out;

    cudaFuncSetAttribute(attn_kernel, cudaFuncAttributeMaxDynamicSharedMemorySize,
                         SM_TOTAL_BYTES);
    cudaFuncSetAttribute(gemm_qkv_kernel, cudaFuncAttributeMaxDynamicSharedMemorySize,
                         GS_BYTES);
    cudaFuncSetAttribute(gemm_o_kernel, cudaFuncAttributeMaxDynamicSharedMemorySize,
                         GS_BYTES);

    preconvert_kernel<<<dim3(4096, 1, 7), 256>>>(Q, K, V, Wq, Wk, Wv, Wo);
    gemm_qkv_kernel<<<dim3(DIM / 128, MROWS / 128, 3), 128, GS_BYTES>>>(bq, bk, bv);
    rope_kernel<<<(MROWS * (DIM / 2)) / 256, 256>>>();
    packv_kernel<<<(BATCH * HEADS * (SEQ / 2) * HD) / 256, 256>>>();
    attn_kernel<<<dim3(16, BATCH * HEADS), 128, SM_TOTAL_BYTES>>>();
    gemm_o_kernel<<<dim3(DIM / 128, MROWS / 128), 128, GS_BYTES>>>(bo, out);
}

// round 17
// speedup vs baseline: 29.6007x; 1.4162x over previous
#include <cuda_runtime.h>
#include <cuda_fp16.h>
#include <math.h>

#define BATCH 2
#define SEQ   2048
#define DIM   1024
#define HEADS 16
#define HD    64
#define MROWS (BATCH*SEQ)   // 4096

// Scratch. Referenced ONLY from device code.
__device__ float    g_qp[MROWS*DIM];    // fp32 projections (rope input)
__device__ float    g_kp[MROWS*DIM];
__device__ float    g_vp[MROWS*DIM];
// fp16 GEMM operands:
__device__ __half   g_qi[MROWS*DIM];    // inputs converted to fp16
__device__ __half   g_ki[MROWS*DIM];
__device__ __half   g_vi[MROWS*DIM];
__device__ unsigned g_wp[4][(DIM/2)*DIM];  // weights packed half2 along k
__device__ __half   g_aoh[MROWS*DIM];   // attention out (fp16, A of gemm_o)
// fp16 attention operands:
__device__ __half   g_qh[MROWS*DIM];    // rope(q)*0.125
__device__ __half   g_kh[MROWS*DIM];    // rope(k)
__device__ __half2  g_vph[BATCH*HEADS*(SEQ/2)*HD];  // V packed (v[2k],v[2k+1])

// ---------------------------------------------------------------------------
// helpers
// ---------------------------------------------------------------------------
__device__ __forceinline__ unsigned h2_u32(__half2 h) {
    union { __half2 h2; unsigned u; } cv;
    cv.h2 = h;
    return cv.u;
}
__device__ __forceinline__ void mma_f16(float d[4], const unsigned a[4],
                                        const unsigned b[2], const float c[4]) {
    asm volatile(
        "mma.sync.aligned.m16n8k16.row.col.f32.f16.f16.f32 "
        "{%0,%1,%2,%3}, {%4,%5,%6,%7}, {%8,%9}, {%10,%11,%12,%13};"
        : "=f"(d[0]), "=f"(d[1]), "=f"(d[2]), "=f"(d[3])
        : "r"(a[0]), "r"(a[1]), "r"(a[2]), "r"(a[3]),
          "r"(b[0]), "r"(b[1]),
          "f"(c[0]), "f"(c[1]), "f"(c[2]), "f"(c[3]));
}
__device__ __forceinline__ void cp16(unsigned* smem_dst, const unsigned* gsrc) {
    unsigned daddr = (unsigned)__cvta_generic_to_shared(smem_dst);
    asm volatile("cp.async.cg.shared.global [%0], [%1], 16;"
                 :: "r"(daddr), "l"(gsrc) : "memory");
}
__device__ __forceinline__ void cp_commit() {
    asm volatile("cp.async.commit_group;" ::: "memory");
}
__device__ __forceinline__ void cp_wait0() {
    asm volatile("cp.async.wait_group 0;" ::: "memory");
}

// ---------------------------------------------------------------------------
// Pre-convert: Q/K/V fp32 -> fp16 natural layout; W -> half2 packed along k.
// grid (4096,1,7): z 0..2 -> Q/K/V (1M float4); z 3..6 -> W (512K words, 2048 blk)
// ---------------------------------------------------------------------------
__global__ void __launch_bounds__(256) preconvert_kernel(
    const float* Q, const float* K, const float* V,
    const float* Wq, const float* Wk, const float* Wv, const float* Wo)
{
    const int z = blockIdx.z;
    if (z < 3) {
        const float* src = (z == 0) ? Q : (z == 1) ? K : V;
        __half* dst = (z == 0) ? g_qi : (z == 1) ? g_ki : g_vi;
        size_t i4 = ((size_t)blockIdx.x * 256 + threadIdx.x);   // float4 index
        float4 v = *(const float4*)(src + i4 * 4);
        uint2 o = make_uint2(h2_u32(__floats2half2_rn(v.x, v.y)),
                             h2_u32(__floats2half2_rn(v.z, v.w)));
        *(uint2*)((unsigned*)dst + i4 * 2) = o;
    } else {
        if (blockIdx.x >= 2048) return;
        const float* W = (z == 3) ? Wq : (z == 4) ? Wk : (z == 5) ? Wv : Wo;
        unsigned* dst = g_wp[z - 3];
        int wi = blockIdx.x * 256 + threadIdx.x;   // 0 .. 524287
        int k2 = wi >> 10;
        int n  = wi & 1023;
        float a = W[(size_t)(2 * k2) * DIM + n];
        float b = W[(size_t)(2 * k2 + 1) * DIM + n];
        dst[wi] = h2_u32(__floats2half2_rn(a, b));
    }
}

// ---------------------------------------------------------------------------
// fp16 GEMM: C[M,N] = A[M,K] @ W[K,N] + bias[N]
// Block 128x128, BK=64 halves, 128 threads = 4 warps (2x2), warp tile 64x64.
// A fp16 [M,K] natural (word = k-pair); W packed half2 along k: Wp[k2][n].
// Smem words: As 128x36 (bank 4r+c), Bs 32x136 (bank 8c+r); double buffered.
// ---------------------------------------------------------------------------
#define GF_AS0 0
#define GF_AS1 4608
#define GF_BS0 9216
#define GF_BS1 13568
#define GF_TOTAL_U32 17920
#define GF_BYTES (GF_TOTAL_U32*4)

__device__ __forceinline__ void gemm_f16_stage(unsigned* As, unsigned* Bs,
                                               const unsigned* __restrict__ A16,
                                               const unsigned* __restrict__ Wp,
                                               int row0, int col0, int k0, int tid)
{
    const int kw = k0 >> 1;                    // word offset in A rows / Wp row idx
#pragma unroll
    for (int i = 0; i < 8; i++) {              // A: 128 rows x 32 words
        int ch = tid + i * 128;
        int rr = ch >> 3;
        int cw = (ch & 7) << 2;
        cp16(As + rr * 36 + cw, A16 + (size_t)(row0 + rr) * 512 + kw + cw);
    }
#pragma unroll
    for (int i = 0; i < 8; i++) {              // B: 32 k2-rows x 128 words
        int ch = tid + i * 128;
        int rr = ch >> 5;
        int cw = (ch & 31) << 2;
        cp16(Bs + rr * 136 + cw, Wp + (size_t)(kw + rr) * 1024 + col0 + cw);
    }
    cp_commit();
}

__device__ __forceinline__ void gemm_f16_body(const unsigned* __restrict__ A16,
                                              const unsigned* __restrict__ Wp,
                                              const float* __restrict__ bias,
                                              float* __restrict__ C)
{
    extern __shared__ unsigned gsm[];

    const int tid  = threadIdx.x;
    const int lane = tid & 31;
    const int warp = tid >> 5;
    const int wm   = warp >> 1;
    const int wn   = warp & 1;
    const int r    = lane >> 2;
    const int c    = lane & 3;
    const int row0 = blockIdx.y * 128;
    const int col0 = blockIdx.x * 128;

    float acc[4][8][4];
#pragma unroll
    for (int mt = 0; mt < 4; mt++)
#pragma unroll
        for (int nt = 0; nt < 8; nt++)
#pragma unroll
            for (int e = 0; e < 4; e++) acc[mt][nt][e] = 0.0f;

    gemm_f16_stage(gsm + GF_AS0, gsm + GF_BS0, A16, Wp, row0, col0, 0, tid);
    cp_wait0();
    __syncthreads();

    for (int k0 = 0; k0 < DIM; k0 += 64) {
        const int cur = (k0 >> 6) & 1;
        unsigned* As = gsm + (cur ? GF_AS1 : GF_AS0);
        unsigned* Bs = gsm + (cur ? GF_BS1 : GF_BS0);
        const bool more = (k0 + 64 < DIM);

        if (more)
            gemm_f16_stage(gsm + (cur ? GF_AS0 : GF_AS1), gsm + (cur ? GF_BS0 : GF_BS1),
                           A16, Wp, row0, col0, k0 + 64, tid);

#pragma unroll
        for (int ks = 0; ks < 4; ks++) {
            const int kw = ks * 8;            // word offset (16 halves per step)
            unsigned a[4][4], b[8][2];
#pragma unroll
            for (int mt = 0; mt < 4; mt++) {
                int m = wm * 64 + mt * 16;
                a[mt][0] = As[(m + r    ) * 36 + kw + c    ];
                a[mt][1] = As[(m + r + 8) * 36 + kw + c    ];
                a[mt][2] = As[(m + r    ) * 36 + kw + c + 4];
                a[mt][3] = As[(m + r + 8) * 36 + kw + c + 4];
            }
#pragma unroll
            for (int nt = 0; nt < 8; nt++) {
                int n = wn * 64 + nt * 8 + r;
                b[nt][0] = Bs[(kw + c    ) * 136 + n];
                b[nt][1] = Bs[(kw + c + 4) * 136 + n];
            }
#pragma unroll
            for (int mt = 0; mt < 4; mt++)
#pragma unroll
                for (int nt = 0; nt < 8; nt++)
                    mma_f16(acc[mt][nt], a[mt], b[nt], acc[mt][nt]);
        }

        if (more) cp_wait0();
        __syncthreads();
    }

#pragma unroll
    for (int nt = 0; nt < 8; nt++) {
        int col = col0 + wn * 64 + nt * 8 + 2 * c;
        float b0 = bias[col], b1 = bias[col + 1];
#pragma unroll
        for (int mt = 0; mt < 4; mt++) {
            int row = row0 + wm * 64 + mt * 16 + r;
            float2 lo = make_float2(acc[mt][nt][0] + b0, acc[mt][nt][1] + b1);
            float2 hi = make_float2(acc[mt][nt][2] + b0, acc[mt][nt][3] + b1);
            *(float2*)(C + (size_t)row * DIM + col)       = lo;
            *(float2*)(C + (size_t)(row + 8) * DIM + col) = hi;
        }
    }
}

__global__ void __launch_bounds__(128) gemm_qkv_kernel(
    const float* bq, const float* bk, const float* bv)
{
    if (blockIdx.z == 0)
        gemm_f16_body((const unsigned*)g_qi, g_wp[0], bq, g_qp);
    else if (blockIdx.z == 1)
        gemm_f16_body((const unsigned*)g_ki, g_wp[1], bk, g_kp);
    else
        gemm_f16_body((const unsigned*)g_vi, g_wp[2], bv, g_vp);
}

__global__ void __launch_bounds__(128) gemm_o_kernel(const float* bo, float* C)
{
    gemm_f16_body((const unsigned*)g_aoh, g_wp[3], bo, C);
}

// ---------------------------------------------------------------------------
// RoPE -> fp16 (q pre-scaled by 1/8). Rotation direction validated R7+.
// ---------------------------------------------------------------------------
__global__ void __launch_bounds__(256) rope_kernel()
{
    int idx = blockIdx.x * blockDim.x + threadIdx.x;
    if (idx >= MROWS * (DIM / 2)) return;
    int m = idx >> 9;
    int cc = idx & 511;
    int h = cc >> 5;
    int d = cc & 31;
    int pos = m & (SEQ - 1);

    float invf = 1.0f / powf(10000.0f, (float)d * (1.0f / 32.0f));
    float ang  = (float)pos * invf;
    float cs, sn;
    sincosf(ang, &cs, &sn);

    int base = m * DIM + h * HD + d;
    float q1 = g_qp[base], q2 = g_qp[base + 32];
    g_qh[base]      = __float2half_rn((q1 * cs + q2 * sn) * 0.125f);
    g_qh[base + 32] = __float2half_rn((q2 * cs - q1 * sn) * 0.125f);
    float k1 = g_kp[base], k2 = g_kp[base + 32];
    g_kh[base]      = __float2half_rn(k1 * cs + k2 * sn);
    g_kh[base + 32] = __float2half_rn(k2 * cs - k1 * sn);
}

// ---------------------------------------------------------------------------
// Pack V into fp16 half2 pairs along the key dim.
// ---------------------------------------------------------------------------
__global__ void __launch_bounds__(256) packv_kernel()
{
    int idx = blockIdx.x * 256 + threadIdx.x;
    int d  = idx & 63;
    int l2 = (idx >> 6) & 1023;
    int bh = idx >> 16;
    int b  = bh >> 4;
    int h  = bh & 15;
    size_t g0 = (size_t)(b * SEQ + 2 * l2) * DIM + h * HD + d;
    float v0 = g_vp[g0];
    float v1 = g_vp[g0 + DIM];
    g_vph[idx] = __floats2half2_rn(v0, v1);
}

// ---------------------------------------------------------------------------
// fp16 flash attention (validated R16); output now written as fp16 (g_aoh).
// ---------------------------------------------------------------------------
#define AQ  0
#define AK0 2304
#define AK1 4608
#define AV0 6912
#define AV1 9216
#define AP  11520
#define SM_TOTAL_U32 13824
#define SM_TOTAL_BYTES (SM_TOTAL_U32*4)

__device__ __forceinline__ void attn_stage_kv(unsigned* Kd, unsigned* Vd,
                                              int b, int h, int k0, int tid)
{
    const unsigned* ku32 = (const unsigned*)g_kh;
    const unsigned* vu32 = (const unsigned*)g_vph;
#pragma unroll
    for (int i = 0; i < 4; i++) {
        int ch = tid + i * 128;
        int rr = ch >> 3;
        int cw = (ch & 7) << 2;
        cp16(Kd + rr * 36 + cw,
             ku32 + (size_t)(b * SEQ + k0 + rr) * 512 + h * 32 + cw);
    }
#pragma unroll
    for (int i = 0; i < 4; i++) {
        int ch = tid + i * 128;
        int rr = ch >> 4;
        int cw = (ch & 15) << 2;
        cp16(Vd + rr * 72 + cw,
             vu32 + ((size_t)(b * HEADS + h) * 1024 + (k0 >> 1) + rr) * 64 + cw);
    }
    cp_commit();
}

__device__ __forceinline__ void attn_one(int qt, int b, int h, unsigned* sm)
{
    const int tid  = threadIdx.x;
    const int lane = tid & 31;
    const int warp = tid >> 5;
    const int r    = lane >> 2;
    const int c    = lane & 3;
    const int w16  = warp * 16;
    const int q0   = qt * 64;

    unsigned* Qs = sm + AQ;
    unsigned* Ps = sm + AP;
    const unsigned* qu32 = (const unsigned*)g_qh;

    __syncthreads();

    attn_stage_kv(sm + AK0, sm + AV0, b, h, 0, tid);
#pragma unroll
    for (int i = 0; i < 4; i++) {
        int ch = tid + i * 128;
        int rr = ch >> 3;
        int cw = (ch & 7) << 2;
        cp16(Qs + rr * 36 + cw,
             qu32 + (size_t)(b * SEQ + q0 + rr) * 512 + h * 32 + cw);
    }
    cp_commit();
    cp_wait0();
    __syncthreads();

    unsigned qa[4][4];
#pragma unroll
    for (int ks = 0; ks < 4; ks++) {
        const int kk = ks * 8;
        qa[ks][0] = Qs[(w16 + r    ) * 36 + kk + c    ];
        qa[ks][1] = Qs[(w16 + r + 8) * 36 + kk + c    ];
        qa[ks][2] = Qs[(w16 + r    ) * 36 + kk + c + 4];
        qa[ks][3] = Qs[(w16 + r + 8) * 36 + kk + c + 4];
    }

    float o[8][4];
#pragma unroll
    for (int nt = 0; nt < 8; nt++)
#pragma unroll
        for (int e = 0; e < 4; e++) o[nt][e] = 0.0f;
    float m_a = -1e30f, m_b = -1e30f, l_a = 0.0f, l_b = 0.0f;

    for (int jt = 0; jt <= qt; jt++) {
        const int cur = jt & 1;
        unsigned* Ks = sm + (cur ? AK1 : AK0);
        unsigned* Vs = sm + (cur ? AV1 : AV0);

        if (jt < qt)
            attn_stage_kv(sm + (cur ? AK0 : AK1), sm + (cur ? AV0 : AV1),
                          b, h, (jt + 1) * 64, tid);

        float s[8][4];
#pragma unroll
        for (int nt = 0; nt < 8; nt++)
#pragma unroll
            for (int e = 0; e < 4; e++) s[nt][e] = 0.0f;

#pragma unroll
        for (int ks = 0; ks < 4; ks++) {
            const int kk = ks * 8;
#pragma unroll
            for (int nt = 0; nt < 8; nt++) {
                unsigned bf[2] = { Ks[(nt * 8 + r) * 36 + kk + c    ],
                                   Ks[(nt * 8 + r) * 36 + kk + c + 4] };
                mma_f16(s[nt], qa[ks], bf, s[nt]);
            }
        }

        if (jt == qt) {
            const int ra = w16 + r, rb = ra + 8;
#pragma unroll
            for (int nt = 0; nt < 8; nt++) {
                int c0_ = nt * 8 + 2 * c;
                if (c0_     > ra) s[nt][0] = -1e30f;
                if (c0_ + 1 > ra) s[nt][1] = -1e30f;
                if (c0_     > rb) s[nt][2] = -1e30f;
                if (c0_ + 1 > rb) s[nt][3] = -1e30f;
            }
        }

        float mxa = -1e30f, mxb = -1e30f;
#pragma unroll
        for (int nt = 0; nt < 8; nt++) {
            mxa = fmaxf(mxa, fmaxf(s[nt][0], s[nt][1]));
            mxb = fmaxf(mxb, fmaxf(s[nt][2], s[nt][3]));
        }
        mxa = fmaxf(mxa, __shfl_xor_sync(0xffffffffu, mxa, 1));
        mxa = fmaxf(mxa, __shfl_xor_sync(0xffffffffu, mxa, 2));
        mxb = fmaxf(mxb, __shfl_xor_sync(0xffffffffu, mxb, 1));
        mxb = fmaxf(mxb, __shfl_xor_sync(0xffffffffu, mxb, 2));

        float mna = fmaxf(m_a, mxa), mnb = fmaxf(m_b, mxb);
        float corra = __expf(m_a - mna), corrb = __expf(m_b - mnb);
        m_a = mna; m_b = mnb;

        float ra_ = 0.0f, rb_ = 0.0f;
#pragma unroll
        for (int nt = 0; nt < 8; nt++) {
            s[nt][0] = __expf(s[nt][0] - m_a);
            s[nt][1] = __expf(s[nt][1] - m_a);
            s[nt][2] = __expf(s[nt][2] - m_b);
            s[nt][3] = __expf(s[nt][3] - m_b);
            ra_ += s[nt][0] + s[nt][1];
            rb_ += s[nt][2] + s[nt][3];
        }
        ra_ += __shfl_xor_sync(0xffffffffu, ra_, 1);
        ra_ += __shfl_xor_sync(0xffffffffu, ra_, 2);
        rb_ += __shfl_xor_sync(0xffffffffu, rb_, 1);
        rb_ += __shfl_xor_sync(0xffffffffu, rb_, 2);
        l_a = l_a * corra + ra_;
        l_b = l_b * corrb + rb_;

#pragma unroll
        for (int nt = 0; nt < 8; nt++) {
            o[nt][0] *= corra; o[nt][1] *= corra;
            o[nt][2] *= corrb; o[nt][3] *= corrb;
        }

#pragma unroll
        for (int nt = 0; nt < 8; nt++) {
            Ps[(w16 + r    ) * 36 + 4 * nt + c] =
                h2_u32(__floats2half2_rn(s[nt][0], s[nt][1]));
            Ps[(w16 + r + 8) * 36 + 4 * nt + c] =
                h2_u32(__floats2half2_rn(s[nt][2], s[nt][3]));
        }
        __syncwarp();

#pragma unroll
        for (int ks = 0; ks < 4; ks++) {
            const int kk  = ks * 8;
            unsigned a[4] = { Ps[(w16 + r    ) * 36 + kk + c    ],
                              Ps[(w16 + r + 8) * 36 + kk + c    ],
                              Ps[(w16 + r    ) * 36 + kk + c + 4],
                              Ps[(w16 + r + 8) * 36 + kk + c + 4] };
#pragma unroll
            for (int nt = 0; nt < 8; nt++) {
                unsigned bf[2] = { Vs[(kk + c    ) * 72 + nt * 8 + r],
                                   Vs[(kk + c + 4) * 72 + nt * 8 + r] };
                mma_f16(o[nt], a, bf, o[nt]);
            }
        }

        if (jt < qt) { cp_wait0(); __syncthreads(); }
    }

    // Write O as fp16 (A-operand of gemm_o). d0,d1 = cols 2c,2c+1 -> one half2.
    float ia = 1.0f / l_a, ib = 1.0f / l_b;
    unsigned* aou = (unsigned*)g_aoh;
    size_t rowa = (size_t)(b * SEQ + q0 + w16 + r) * 512 + (size_t)h * 32;
#pragma unroll
    for (int nt = 0; nt < 8; nt++) {
        int colw = nt * 4 + c;
        aou[rowa + colw] =
            h2_u32(__floats2half2_rn(o[nt][0] * ia, o[nt][1] * ia));
        aou[rowa + 8 * 512 + colw] =
            h2_u32(__floats2half2_rn(o[nt][2] * ib, o[nt][3] * ib));
    }
}

__global__ void __launch_bounds__(128, 3) attn_kernel()
{
    extern __shared__ unsigned sm[];
    const int bh = blockIdx.y;
    const int b  = bh >> 4;
    const int h  = bh & 15;

    attn_one(blockIdx.x,      b, h, sm);
    attn_one(31 - blockIdx.x, b, h, sm);
}

// ---------------------------------------------------------------------------
extern "C" void kernel_launch(void* const* d_in, const int* in_sizes, int n_in,
                              void* d_out, int out_size)
{
    const float* Q  = (const float*)d_in[0];
    const float* K  = (const float*)d_in[1];
    const float* V  = (const float*)d_in[2];
    const float* Wq = (const float*)d_in[3];
    const float* Wk = (const float*)d_in[4];
    const float* Wv = (const float*)d_in[5];
    const float* Wo = (const float*)d_in[6];
    const float* bq = (const float*)d_in[7];
    const float* bk = (const float*)d_in[8];
    const float* bv = (const float*)d_in[9];
    const float* bo = (const float*)d_in[10];
    float* out = (float*)d_out;

    cudaFuncSetAttribute(attn_kernel, cudaFuncAttributeMaxDynamicSharedMemorySize,
                         SM_TOTAL_BYTES);
    cudaFuncSetAttribute(gemm_qkv_kernel, cudaFuncAttributeMaxDynamicSharedMemorySize,
                         GF_BYTES);
    cudaFuncSetAttribute(gemm_o_kernel, cudaFuncAttributeMaxDynamicSharedMemorySize,
                         GF_BYTES);

    preconvert_kernel<<<dim3(4096, 1, 7), 256>>>(Q, K, V, Wq, Wk, Wv, Wo);
    gemm_qkv_kernel<<<dim3(DIM / 128, MROWS / 128, 3), 128, GF_BYTES>>>(bq, bk, bv);
    rope_kernel<<<(MROWS * (DIM / 2)) / 256, 256>>>();
    packv_kernel<<<(BATCH * HEADS * (SEQ / 2) * HD) / 256, 256>>>();
    attn_kernel<<<dim3(16, BATCH * HEADS), 128, SM_TOTAL_BYTES>>>();
    gemm_o_kernel<<<dim3(DIM / 128, MROWS / 128), 128, GF_BYTES>>>(bo, out);
}